// round 5
// baseline (speedup 1.0000x reference)
#include <cuda_runtime.h>
#include <cstdint>

// Problem constants
#define Bq 2
#define Sq 2048
#define Eq 1024
#define Hq 16
#define Dq 64
#define KKq 409           // max(1, int(S*0.2))
#define SCOREMUL 0.15625f // (1/sqrt(64)) / temperature, temperature = 0.8
#define DIAGMUL  1.15f    // 1 + ACH*0.3
#define MASKMUL  1.15f    // 1 + (-DA)*0.3

#define TM 16             // query rows per attention block
#define SCPAD 18          // scT row pad

// ---------------------------------------------------------------------------
// Scratch (device globals)
// ---------------------------------------------------------------------------
__device__ float g_Q [Bq*Hq*Sq*Dq];   // (b,h,s,d)
__device__ float g_K [Bq*Hq*Sq*Dq];   // (b,h,s,d), pre-scaled by time_scales
__device__ float g_V [Bq*Hq*Sq*Dq];   // (b,h,s,d)
__device__ float g_O [Bq*Sq*Eq];      // (b,s,e)
__device__ float g_Wt[4*Eq*Eq];       // Wq^T, Wk^T, Wv^T, Wo^T

// ---------------------------------------------------------------------------
// bf16x2 helpers
// ---------------------------------------------------------------------------
__device__ __forceinline__ uint32_t bfpack(float lo, float hi) {
    uint32_t r;
    asm("cvt.rn.bf16x2.f32 %0, %1, %2;" : "=r"(r) : "f"(hi), "f"(lo));
    return r;   // low 16 bits = lo, high 16 bits = hi
}
__device__ __forceinline__ float bflowf(uint32_t p)  { return __uint_as_float(p << 16); }
__device__ __forceinline__ float bfhighf(uint32_t p) { return __uint_as_float(p & 0xFFFF0000u); }

__device__ __forceinline__ void mma_bf16(float* d, const uint32_t* a, uint32_t b0, uint32_t b1) {
    asm volatile(
        "mma.sync.aligned.m16n8k16.row.col.f32.bf16.bf16.f32 "
        "{%0,%1,%2,%3}, {%4,%5,%6,%7}, {%8,%9}, {%0,%1,%2,%3};"
        : "+f"(d[0]), "+f"(d[1]), "+f"(d[2]), "+f"(d[3])
        : "r"(a[0]), "r"(a[1]), "r"(a[2]), "r"(a[3]), "r"(b0), "r"(b1));
}

// ---------------------------------------------------------------------------
// Monotonic float->uint map
// ---------------------------------------------------------------------------
__device__ __forceinline__ unsigned fmap(float f) {
    unsigned u = __float_as_uint(f);
    return (u & 0x80000000u) ? ~u : (u | 0x80000000u);
}

// ---------------------------------------------------------------------------
// Weight transpose: g_Wt[z] = W(z)^T
// ---------------------------------------------------------------------------
__global__ void wtrans_kernel(const float* __restrict__ Wq, const float* __restrict__ Wk,
                              const float* __restrict__ Wv, const float* __restrict__ Wo)
{
    __shared__ float t[32][33];
    const int z = blockIdx.z;
    const float* W = (z == 0) ? Wq : (z == 1) ? Wk : (z == 2) ? Wv : Wo;
    float* out = g_Wt + (size_t)z * Eq * Eq;
    const int x0 = blockIdx.x * 32, y0 = blockIdx.y * 32;
    const int tx = threadIdx.x, ty = threadIdx.y;
    #pragma unroll
    for (int i = 0; i < 32; i += 8)
        t[ty + i][tx] = W[(size_t)(y0 + ty + i) * Eq + x0 + tx];
    __syncthreads();
    #pragma unroll
    for (int i = 0; i < 32; i += 8)
        out[(size_t)(x0 + ty + i) * Eq + y0 + tx] = t[tx][ty + i];
}

// ---------------------------------------------------------------------------
// bf16x3 mma.sync GEMM: C[m][n] = sum_k A[m][k] * Bt[n][k]  (+ mode epilogue)
//   mode 0: A=query, Bt=Wq^T -> g_Q  (b,h,s,d), +bq
//   mode 1: A=key,   Bt=Wk^T -> g_K  (b,h,s,d), (+bk)*ts[h]
//   mode 2: A=value, Bt=Wv^T -> g_V  (b,h,s,d), +bv
//   mode 3: A=g_O,   Bt=Wo^T -> Cout row-major, +bo
// ---------------------------------------------------------------------------
#define SROW 20

__global__ __launch_bounds__(256) void gemm_mma_kernel(
    const float* __restrict__ A, const float* __restrict__ Bt,
    const float* __restrict__ bias, const float* __restrict__ ts,
    int mode, float* __restrict__ Cout)
{
    __shared__ uint32_t sb[4 * 128 * SROW];
    uint32_t* Ahi = sb;
    uint32_t* Alo = sb + 128 * SROW;
    uint32_t* Bhi = sb + 2 * 128 * SROW;
    uint32_t* Blo = sb + 3 * 128 * SROW;

    const int tid  = threadIdx.x;
    const int wid  = tid >> 5, lane = tid & 31;
    const int gid  = lane >> 2, tig = lane & 3;
    const int wm   = wid & 3,  wn  = wid >> 2;
    const int m0   = blockIdx.y * 128, n0 = blockIdx.x * 128;

    const float4* pa[4];
    const float4* pb[4];
    int so[4];
    #pragma unroll
    for (int j = 0; j < 4; ++j) {
        int f4  = tid + j * 256;
        int row = f4 >> 3;
        int cq  = f4 & 7;
        pa[j] = (const float4*)(A  + (size_t)(m0 + row) * Eq) + cq;
        pb[j] = (const float4*)(Bt + (size_t)(n0 + row) * Eq) + cq;
        so[j] = row * SROW + cq * 2;
    }

    float4 ra[4], rb[4];
    #pragma unroll
    for (int j = 0; j < 4; ++j) { ra[j] = pa[j][0]; rb[j] = pb[j][0]; }

    float acc[2][8][4];
    #pragma unroll
    for (int mt = 0; mt < 2; ++mt)
        #pragma unroll
        for (int nt = 0; nt < 8; ++nt)
            #pragma unroll
            for (int c = 0; c < 4; ++c) acc[mt][nt][c] = 0.0f;

    for (int kc = 0; kc < 32; ++kc) {
        __syncthreads();
        #pragma unroll
        for (int j = 0; j < 4; ++j) {
            uint32_t h0 = bfpack(ra[j].x, ra[j].y);
            uint32_t h1 = bfpack(ra[j].z, ra[j].w);
            Ahi[so[j]]     = h0;
            Ahi[so[j] + 1] = h1;
            Alo[so[j]]     = bfpack(ra[j].x - bflowf(h0), ra[j].y - bfhighf(h0));
            Alo[so[j] + 1] = bfpack(ra[j].z - bflowf(h1), ra[j].w - bfhighf(h1));
            uint32_t g0 = bfpack(rb[j].x, rb[j].y);
            uint32_t g1 = bfpack(rb[j].z, rb[j].w);
            Bhi[so[j]]     = g0;
            Bhi[so[j] + 1] = g1;
            Blo[so[j]]     = bfpack(rb[j].x - bflowf(g0), rb[j].y - bfhighf(g0));
            Blo[so[j] + 1] = bfpack(rb[j].z - bflowf(g1), rb[j].w - bfhighf(g1));
        }
        __syncthreads();

        if (kc < 31) {
            #pragma unroll
            for (int j = 0; j < 4; ++j) {
                ra[j] = pa[j][(kc + 1) * 8];
                rb[j] = pb[j][(kc + 1) * 8];
            }
        }

        #pragma unroll
        for (int ks = 0; ks < 2; ++ks) {
            const int kb = ks * 8;
            uint32_t ah[2][4], al[2][4];
            #pragma unroll
            for (int mt = 0; mt < 2; ++mt) {
                const int r0 = wm * 32 + mt * 16 + gid;
                ah[mt][0] = Ahi[r0 * SROW + kb + tig];
                ah[mt][1] = Ahi[(r0 + 8) * SROW + kb + tig];
                ah[mt][2] = Ahi[r0 * SROW + kb + tig + 4];
                ah[mt][3] = Ahi[(r0 + 8) * SROW + kb + tig + 4];
                al[mt][0] = Alo[r0 * SROW + kb + tig];
                al[mt][1] = Alo[(r0 + 8) * SROW + kb + tig];
                al[mt][2] = Alo[r0 * SROW + kb + tig + 4];
                al[mt][3] = Alo[(r0 + 8) * SROW + kb + tig + 4];
            }
            #pragma unroll
            for (int nt = 0; nt < 8; ++nt) {
                const int n = wn * 64 + nt * 8 + gid;
                uint32_t bh0 = Bhi[n * SROW + kb + tig];
                uint32_t bh1 = Bhi[n * SROW + kb + tig + 4];
                uint32_t bl0 = Blo[n * SROW + kb + tig];
                uint32_t bl1 = Blo[n * SROW + kb + tig + 4];
                #pragma unroll
                for (int mt = 0; mt < 2; ++mt) {
                    mma_bf16(acc[mt][nt], ah[mt], bh0, bh1);
                    mma_bf16(acc[mt][nt], ah[mt], bl0, bl1);
                    mma_bf16(acc[mt][nt], al[mt], bh0, bh1);
                }
            }
        }
    }

    // ---- epilogue ----
    #pragma unroll
    for (int mt = 0; mt < 2; ++mt) {
        const int row = m0 + wm * 32 + mt * 16 + gid;
        #pragma unroll
        for (int nt = 0; nt < 8; ++nt) {
            const int col = n0 + wn * 64 + nt * 8 + 2 * tig;
            const float* d = acc[mt][nt];
            if (mode == 3) {
                float2 bv = *(const float2*)(bias + col);
                *(float2*)(Cout + (size_t)row * Eq + col) =
                    make_float2(d[0] + bv.x, d[1] + bv.y);
                *(float2*)(Cout + (size_t)(row + 8) * Eq + col) =
                    make_float2(d[2] + bv.x, d[3] + bv.y);
            } else {
                const int bb = row >> 11, s = row & (Sq - 1);
                const int h = col >> 6, dd = col & 63;
                float* base = (mode == 0) ? g_Q : (mode == 1) ? g_K : g_V;
                const float sc = (mode == 1) ? ts[h] : 1.0f;
                float2 bv = *(const float2*)(bias + col);
                float* dst = base + ((size_t)(bb * Hq + h) * Sq + s) * Dq + dd;
                *(float2*)(dst)          = make_float2((d[0] + bv.x) * sc, (d[1] + bv.y) * sc);
                *(float2*)(dst + 8 * Dq) = make_float2((d[2] + bv.x) * sc, (d[3] + bv.y) * sc);
            }
        }
    }
}

// ---------------------------------------------------------------------------
// Fused attention v2 (mma.sync): one block = 16 query rows of one (b,h).
// Smem (floats):
//   scT [2048][18]         scores/probs (s-major)          147,456 B
//   ST  hi/lo u32 stages   K: [256 s][35], V: [64 d][140]   71,680 B
//   Qs  [16][66]           Q tile fp32
//   hist[8][256] u32, inv[16]
// red (PV reduction) aliases scT.
// ---------------------------------------------------------------------------
#define OFF_ST   36864
#define STSZ     8960
#define OFF_QS   (OFF_ST + 2*STSZ)       // 54784
#define OFF_HIST (OFF_QS + 16*66)        // 55840
#define OFF_INV  (OFF_HIST + 2048)       // 57888
#define SMEM_FLOATS (OFF_INV + 16)       // 57904 -> 231,616 B

__global__ __launch_bounds__(256, 1) void attn_kernel()
{
    extern __shared__ float smem[];
    float*    scT  = smem;
    uint32_t* SThi = (uint32_t*)(smem + OFF_ST);
    uint32_t* STlo = SThi + STSZ;
    float*    Qs   = smem + OFF_QS;
    unsigned* hist = (unsigned*)(smem + OFF_HIST);
    float*    inv  = smem + OFF_INV;
    float*    red  = smem;               // alias: used only after PV mma complete

    const int tid  = threadIdx.x;
    const int w    = tid >> 5, lane = tid & 31;
    const int gid  = lane >> 2, tig = lane & 3;
    const int bh   = blockIdx.y;
    const int t0   = blockIdx.x * TM;
    const int b    = bh >> 4, h = bh & 15;

    const float* Qg = g_Q + (size_t)bh * Sq * Dq;
    const float* Kg = g_K + (size_t)bh * Sq * Dq;
    const float* Vg = g_V + (size_t)bh * Sq * Dq;

    // ---- Q stage + A fragments (registers) ----
    for (int i = tid; i < TM * Dq; i += 256) {
        int r = i >> 6, d = i & 63;
        Qs[r * 66 + d] = Qg[(size_t)(t0 + r) * Dq + d];
    }
    __syncthreads();

    uint32_t ahq[4][4], alq[4][4];
    #pragma unroll
    for (int ks = 0; ks < 4; ++ks) {
        float2 q[4];
        q[0] = *(float2*)&Qs[gid * 66 + ks * 16 + 2 * tig];
        q[1] = *(float2*)&Qs[(gid + 8) * 66 + ks * 16 + 2 * tig];
        q[2] = *(float2*)&Qs[gid * 66 + ks * 16 + 2 * tig + 8];
        q[3] = *(float2*)&Qs[(gid + 8) * 66 + ks * 16 + 2 * tig + 8];
        #pragma unroll
        for (int j = 0; j < 4; ++j) {
            uint32_t hh = bfpack(q[j].x, q[j].y);
            ahq[ks][j] = hh;
            alq[ks][j] = bfpack(q[j].x - bflowf(hh), q[j].y - bfhighf(hh));
        }
    }

    // ---- QK^T via mma: 8 chunks of 256 s ----
    for (int c = 0; c < 8; ++c) {
        __syncthreads();
        for (int i = tid; i < 8192; i += 256) {
            int s = i >> 5, d2 = i & 31;
            float2 kv = *(const float2*)(Kg + (size_t)(c * 256 + s) * Dq + 2 * d2);
            uint32_t hh = bfpack(kv.x, kv.y);
            SThi[s * 35 + d2] = hh;
            STlo[s * 35 + d2] = bfpack(kv.x - bflowf(hh), kv.y - bfhighf(hh));
        }
        __syncthreads();

        #pragma unroll
        for (int nt = 0; nt < 4; ++nt) {
            const int sl = w * 32 + nt * 8 + gid;          // B fragment row (n)
            float cf[4] = {0.f, 0.f, 0.f, 0.f};
            #pragma unroll
            for (int ks = 0; ks < 4; ++ks) {
                uint32_t b0h = SThi[sl * 35 + ks * 8 + tig];
                uint32_t b1h = SThi[sl * 35 + ks * 8 + 4 + tig];
                uint32_t b0l = STlo[sl * 35 + ks * 8 + tig];
                uint32_t b1l = STlo[sl * 35 + ks * 8 + 4 + tig];
                mma_bf16(cf, ahq[ks], b0h, b1h);
                mma_bf16(cf, ahq[ks], b0l, b1l);
                mma_bf16(cf, alq[ks], b0h, b1h);
            }
            const int sg = c * 256 + w * 32 + nt * 8 + 2 * tig;
            float v0 = cf[0] * SCOREMUL; if (sg     == t0 + gid)     v0 *= DIAGMUL;
            float v1 = cf[1] * SCOREMUL; if (sg + 1 == t0 + gid)     v1 *= DIAGMUL;
            float v2 = cf[2] * SCOREMUL; if (sg     == t0 + gid + 8) v2 *= DIAGMUL;
            float v3 = cf[3] * SCOREMUL; if (sg + 1 == t0 + gid + 8) v3 *= DIAGMUL;
            scT[sg * SCPAD + gid]           = v0;
            scT[(sg + 1) * SCPAD + gid]     = v1;
            scT[sg * SCPAD + gid + 8]       = v2;
            scT[(sg + 1) * SCPAD + gid + 8] = v3;
        }
    }
    __syncthreads();

    // ---- per-row: filtered exact top-k (radix select) + softmax ----
    {
        unsigned* hw = hist + w * 256;

        for (int rr = 0; rr < 2; ++rr) {
            const int r = w * 2 + rr;

            // sweep 1: mean/std -> filter level L
            float s1 = 0.f, s2 = 0.f;
            for (int i = lane; i < Sq; i += 32) {
                float v = scT[i * SCPAD + r];
                s1 += v; s2 += v * v;
            }
            #pragma unroll
            for (int o = 16; o; o >>= 1) {
                s1 += __shfl_xor_sync(0xFFFFFFFFu, s1, o);
                s2 += __shfl_xor_sync(0xFFFFFFFFu, s2, o);
            }
            const float mu  = s1 * (1.0f / 2048.0f);
            const float var = fmaxf(s2 * (1.0f / 2048.0f) - mu * mu, 0.0f);
            const float L   = mu + 0.6f * sqrtf(var);

            // sweep 2: validate filter (top-K must be inside {x >= L})
            int n = 0;
            for (int i = lane; i < Sq; i += 32)
                n += (scT[i * SCPAD + r] >= L) ? 1 : 0;
            #pragma unroll
            for (int o = 16; o; o >>= 1) n += __shfl_xor_sync(0xFFFFFFFFu, n, o);
            const unsigned uL = (n >= KKq) ? fmap(L) : 0u;

            // exact radix select on the filtered multiset
            unsigned thrp = 0;
            int kneed = KKq;
            for (int shift = 24; shift >= 0; shift -= 8) {
                #pragma unroll
                for (int j = 0; j < 8; ++j) hw[lane + j * 32] = 0;
                __syncwarp();
                for (int i = lane; i < Sq; i += 32) {
                    unsigned u = fmap(scT[i * SCPAD + r]);
                    bool ok = (u >= uL) &&
                              ((shift == 24) || (((u ^ thrp) >> (shift + 8)) == 0));
                    unsigned act = __ballot_sync(0xFFFFFFFFu, ok);
                    if (ok) {
                        int bin = (u >> shift) & 255;
                        unsigned peers = __match_any_sync(act, bin);
                        if ((int)lane == __ffs(peers) - 1)
                            atomicAdd(&hw[bin], (unsigned)__popc(peers));
                    }
                }
                __syncwarp();
                const int b0 = (31 - lane) * 8;
                unsigned cb[8], cl = 0;
                #pragma unroll
                for (int j = 0; j < 8; ++j) { cb[j] = hw[b0 + j]; cl += cb[j]; }
                unsigned S = cl;
                #pragma unroll
                for (int o = 1; o < 32; o <<= 1) {
                    unsigned x = __shfl_up_sync(0xFFFFFFFFu, S, o);
                    if (lane >= o) S += x;
                }
                unsigned excl = S - cl;
                bool has = (excl < (unsigned)kneed) && ((unsigned)kneed <= S);
                unsigned bal = __ballot_sync(0xFFFFFFFFu, has);
                int src = __ffs(bal) - 1;
                int bsel = 0, nk = 0;
                if (lane == src) {
                    int rem = kneed - (int)excl;
                    #pragma unroll
                    for (int j = 7; j >= 0; --j) {
                        int cnt = (int)cb[j];
                        if (rem <= cnt) { bsel = b0 + j; nk = rem; break; }
                        rem -= cnt;
                    }
                }
                bsel  = __shfl_sync(0xFFFFFFFFu, bsel, src);
                nk    = __shfl_sync(0xFFFFFFFFu, nk, src);
                thrp |= ((unsigned)bsel) << shift;
                kneed = nk;
                __syncwarp();
            }

            // boost + max
            float mx = -3.402823466e+38f;
            for (int i = lane; i < Sq; i += 32) {
                float v = scT[i * SCPAD + r];
                if (fmap(v) >= thrp) v *= MASKMUL;
                scT[i * SCPAD + r] = v;
                mx = fmaxf(mx, v);
            }
            #pragma unroll
            for (int o = 16; o; o >>= 1) mx = fmaxf(mx, __shfl_xor_sync(0xFFFFFFFFu, mx, o));

            // exp + sum
            float sum = 0.0f;
            for (int i = lane; i < Sq; i += 32) {
                float e = __expf(scT[i * SCPAD + r] - mx);
                scT[i * SCPAD + r] = e;
                sum += e;
            }
            #pragma unroll
            for (int o = 16; o; o >>= 1) sum += __shfl_xor_sync(0xFFFFFFFFu, sum, o);
            if (lane == 0) inv[r] = 1.0f / sum;
        }
    }

    // ---- P @ V via mma: per-warp k-slice, accumulate across 8 chunks ----
    float cacc[8][4];
    #pragma unroll
    for (int nt = 0; nt < 8; ++nt)
        #pragma unroll
        for (int j = 0; j < 4; ++j) cacc[nt][j] = 0.0f;

    for (int c = 0; c < 8; ++c) {
        __syncthreads();
        for (int i = tid; i < 8192; i += 256) {
            int d = i & 63, s2 = i >> 6;
            float v0 = Vg[(size_t)(c * 256 + 2 * s2)     * Dq + d];
            float v1 = Vg[(size_t)(c * 256 + 2 * s2 + 1) * Dq + d];
            uint32_t hh = bfpack(v0, v1);
            SThi[d * 140 + s2] = hh;
            STlo[d * 140 + s2] = bfpack(v0 - bflowf(hh), v1 - bfhighf(hh));
        }
        __syncthreads();

        #pragma unroll
        for (int kk = 0; kk < 2; ++kk) {
            const int sg  = c * 256 + (w * 2 + kk) * 16;
            const int s2b = (w * 2 + kk) * 8;
            uint32_t ah[4], al[4];
            {
                float pa, pb; uint32_t hh;
                pa = scT[(sg + 2 * tig) * SCPAD + gid];
                pb = scT[(sg + 2 * tig + 1) * SCPAD + gid];
                hh = bfpack(pa, pb); ah[0] = hh;
                al[0] = bfpack(pa - bflowf(hh), pb - bfhighf(hh));
                pa = scT[(sg + 2 * tig) * SCPAD + gid + 8];
                pb = scT[(sg + 2 * tig + 1) * SCPAD + gid + 8];
                hh = bfpack(pa, pb); ah[1] = hh;
                al[1] = bfpack(pa - bflowf(hh), pb - bfhighf(hh));
                pa = scT[(sg + 2 * tig + 8) * SCPAD + gid];
                pb = scT[(sg + 2 * tig + 9) * SCPAD + gid];
                hh = bfpack(pa, pb); ah[2] = hh;
                al[2] = bfpack(pa - bflowf(hh), pb - bfhighf(hh));
                pa = scT[(sg + 2 * tig + 8) * SCPAD + gid + 8];
                pb = scT[(sg + 2 * tig + 9) * SCPAD + gid + 8];
                hh = bfpack(pa, pb); ah[3] = hh;
                al[3] = bfpack(pa - bflowf(hh), pb - bfhighf(hh));
            }
            #pragma unroll
            for (int nt = 0; nt < 8; ++nt) {
                const int dd = nt * 8 + gid;
                uint32_t b0h = SThi[dd * 140 + s2b + tig];
                uint32_t b1h = SThi[dd * 140 + s2b + 4 + tig];
                uint32_t b0l = STlo[dd * 140 + s2b + tig];
                uint32_t b1l = STlo[dd * 140 + s2b + 4 + tig];
                mma_bf16(cacc[nt], ah, b0h, b1h);
                mma_bf16(cacc[nt], ah, b0l, b1l);
                mma_bf16(cacc[nt], al, b0h, b1h);
            }
        }
    }
    __syncthreads();   // all PV reads of scT done -> safe to alias as red

    #pragma unroll
    for (int nt = 0; nt < 8; ++nt) {
        red[w * 1040 + gid * 65 + nt * 8 + 2 * tig]           = cacc[nt][0];
        red[w * 1040 + gid * 65 + nt * 8 + 2 * tig + 1]       = cacc[nt][1];
        red[w * 1040 + (gid + 8) * 65 + nt * 8 + 2 * tig]     = cacc[nt][2];
        red[w * 1040 + (gid + 8) * 65 + nt * 8 + 2 * tig + 1] = cacc[nt][3];
    }
    __syncthreads();

    for (int i = tid; i < TM * Dq; i += 256) {
        int t = i >> 6, d = i & 63;
        float o = 0.f;
        #pragma unroll
        for (int ww = 0; ww < 8; ++ww) o += red[ww * 1040 + t * 65 + d];
        g_O[((size_t)(b * Sq + t0 + t)) * Eq + h * Dq + d] = o * inv[t];
    }
}

// ---------------------------------------------------------------------------
// Launch
// ---------------------------------------------------------------------------
extern "C" void kernel_launch(void* const* d_in, const int* in_sizes, int n_in,
                              void* d_out, int out_size)
{
    const float* query = (const float*)d_in[0];
    const float* key   = (const float*)d_in[1];
    const float* value = (const float*)d_in[2];
    const float* Wq    = (const float*)d_in[3];
    const float* bq    = (const float*)d_in[4];
    const float* Wk    = (const float*)d_in[5];
    const float* bk    = (const float*)d_in[6];
    const float* Wv    = (const float*)d_in[7];
    const float* bv    = (const float*)d_in[8];
    const float* Wo    = (const float*)d_in[9];
    const float* bo    = (const float*)d_in[10];
    const float* ts    = (const float*)d_in[11];

    cudaFuncSetAttribute(attn_kernel, cudaFuncAttributeMaxDynamicSharedMemorySize,
                         SMEM_FLOATS * 4);

    dim3 gT(Eq / 32, Eq / 32, 4);
    wtrans_kernel<<<gT, dim3(32, 8)>>>(Wq, Wk, Wv, Wo);

    float* wt; cudaGetSymbolAddress((void**)&wt, g_Wt);
    float* gO; cudaGetSymbolAddress((void**)&gO, g_O);

    dim3 gA(Eq / 128, (Bq * Sq) / 128);

    gemm_mma_kernel<<<gA, 256>>>(query, wt + 0 * (size_t)Eq * Eq, bq, ts, 0, nullptr);
    gemm_mma_kernel<<<gA, 256>>>(key,   wt + 1 * (size_t)Eq * Eq, bk, ts, 1, nullptr);
    gemm_mma_kernel<<<gA, 256>>>(value, wt + 2 * (size_t)Eq * Eq, bv, ts, 2, nullptr);

    dim3 gAttn(Sq / TM, Bq * Hq);
    attn_kernel<<<gAttn, 256, SMEM_FLOATS * 4>>>();

    gemm_mma_kernel<<<gA, 256>>>(gO, wt + 3 * (size_t)Eq * Eq, bo, ts, 3, (float*)d_out);
}

// round 6
// speedup vs baseline: 1.4737x; 1.4737x over previous
#include <cuda_runtime.h>
#include <cstdint>

// Problem constants
#define Bq 2
#define Sq 2048
#define Eq 1024
#define Hq 16
#define Dq 64
#define KKq 409           // max(1, int(S*0.2))
#define SCOREMUL 0.15625f // (1/sqrt(64)) / temperature, temperature = 0.8
#define DIAGMUL  1.15f    // 1 + ACH*0.3
#define MASKMUL  1.15f    // 1 + (-DA)*0.3

#define TM 16             // query rows per attention block
#define SCPAD 18          // scT row pad

// ---------------------------------------------------------------------------
// Scratch (device globals)
// ---------------------------------------------------------------------------
__device__ float g_Q [Bq*Hq*Sq*Dq];   // (b,h,s,d)
__device__ float g_Kt[Bq*Hq*Dq*Sq];   // (b,h,d,s)  transposed, pre-scaled by time_scales
__device__ float g_V [Bq*Hq*Sq*Dq];   // (b,h,s,d)
__device__ float g_O [Bq*Sq*Eq];      // (b,s,e)
__device__ float g_Wt[4*Eq*Eq];       // Wq^T, Wk^T, Wv^T, Wo^T

// ---------------------------------------------------------------------------
// bf16x2 helpers
// ---------------------------------------------------------------------------
__device__ __forceinline__ uint32_t bfpack(float lo, float hi) {
    uint32_t r;
    asm("cvt.rn.bf16x2.f32 %0, %1, %2;" : "=r"(r) : "f"(hi), "f"(lo));
    return r;
}
__device__ __forceinline__ float bflowf(uint32_t p)  { return __uint_as_float(p << 16); }
__device__ __forceinline__ float bfhighf(uint32_t p) { return __uint_as_float(p & 0xFFFF0000u); }

__device__ __forceinline__ void mma_bf16(float* d, const uint32_t* a, uint32_t b0, uint32_t b1) {
    asm volatile(
        "mma.sync.aligned.m16n8k16.row.col.f32.bf16.bf16.f32 "
        "{%0,%1,%2,%3}, {%4,%5,%6,%7}, {%8,%9}, {%0,%1,%2,%3};"
        : "+f"(d[0]), "+f"(d[1]), "+f"(d[2]), "+f"(d[3])
        : "r"(a[0]), "r"(a[1]), "r"(a[2]), "r"(a[3]), "r"(b0), "r"(b1));
}

// ---------------------------------------------------------------------------
// Monotonic float->uint map
// ---------------------------------------------------------------------------
__device__ __forceinline__ unsigned fmap(float f) {
    unsigned u = __float_as_uint(f);
    return (u & 0x80000000u) ? ~u : (u | 0x80000000u);
}

// ---------------------------------------------------------------------------
// Weight transpose: g_Wt[z] = W(z)^T
// ---------------------------------------------------------------------------
__global__ void wtrans_kernel(const float* __restrict__ Wq, const float* __restrict__ Wk,
                              const float* __restrict__ Wv, const float* __restrict__ Wo)
{
    __shared__ float t[32][33];
    const int z = blockIdx.z;
    const float* W = (z == 0) ? Wq : (z == 1) ? Wk : (z == 2) ? Wv : Wo;
    float* out = g_Wt + (size_t)z * Eq * Eq;
    const int x0 = blockIdx.x * 32, y0 = blockIdx.y * 32;
    const int tx = threadIdx.x, ty = threadIdx.y;
    #pragma unroll
    for (int i = 0; i < 32; i += 8)
        t[ty + i][tx] = W[(size_t)(y0 + ty + i) * Eq + x0 + tx];
    __syncthreads();
    #pragma unroll
    for (int i = 0; i < 32; i += 8)
        out[(size_t)(x0 + ty + i) * Eq + y0 + tx] = t[tx][ty + i];
}

// ---------------------------------------------------------------------------
// bf16x3 mma.sync GEMM (R4, proven): C[m][n] = sum_k A[m][k] * Bt[n][k]
//   mode 0: A=query, Bt=Wq^T -> g_Q  (b,h,s,d), +bq
//   mode 1: A=Wk^T,  Bt=key  -> g_Kt (b,h,d,s), (+bk)*ts[h]
//   mode 2: A=value, Bt=Wv^T -> g_V  (b,h,s,d), +bv
//   mode 3: A=g_O,   Bt=Wo^T -> Cout row-major, +bo
// ---------------------------------------------------------------------------
#define SROW 20

__global__ __launch_bounds__(256) void gemm_mma_kernel(
    const float* __restrict__ A, const float* __restrict__ Bt,
    const float* __restrict__ bias, const float* __restrict__ ts,
    int mode, float* __restrict__ Cout)
{
    __shared__ uint32_t sb[4 * 128 * SROW];
    uint32_t* Ahi = sb;
    uint32_t* Alo = sb + 128 * SROW;
    uint32_t* Bhi = sb + 2 * 128 * SROW;
    uint32_t* Blo = sb + 3 * 128 * SROW;

    const int tid  = threadIdx.x;
    const int wid  = tid >> 5, lane = tid & 31;
    const int gid  = lane >> 2, tig = lane & 3;
    const int wm   = wid & 3,  wn  = wid >> 2;
    const int m0   = blockIdx.y * 128, n0 = blockIdx.x * 128;

    const float4* pa[4];
    const float4* pb[4];
    int so[4];
    #pragma unroll
    for (int j = 0; j < 4; ++j) {
        int f4  = tid + j * 256;
        int row = f4 >> 3;
        int cq  = f4 & 7;
        pa[j] = (const float4*)(A  + (size_t)(m0 + row) * Eq) + cq;
        pb[j] = (const float4*)(Bt + (size_t)(n0 + row) * Eq) + cq;
        so[j] = row * SROW + cq * 2;
    }

    float4 ra[4], rb[4];
    #pragma unroll
    for (int j = 0; j < 4; ++j) { ra[j] = pa[j][0]; rb[j] = pb[j][0]; }

    float acc[2][8][4];
    #pragma unroll
    for (int mt = 0; mt < 2; ++mt)
        #pragma unroll
        for (int nt = 0; nt < 8; ++nt)
            #pragma unroll
            for (int c = 0; c < 4; ++c) acc[mt][nt][c] = 0.0f;

    for (int kc = 0; kc < 32; ++kc) {
        __syncthreads();
        #pragma unroll
        for (int j = 0; j < 4; ++j) {
            uint32_t h0 = bfpack(ra[j].x, ra[j].y);
            uint32_t h1 = bfpack(ra[j].z, ra[j].w);
            Ahi[so[j]]     = h0;
            Ahi[so[j] + 1] = h1;
            Alo[so[j]]     = bfpack(ra[j].x - bflowf(h0), ra[j].y - bfhighf(h0));
            Alo[so[j] + 1] = bfpack(ra[j].z - bflowf(h1), ra[j].w - bfhighf(h1));
            uint32_t g0 = bfpack(rb[j].x, rb[j].y);
            uint32_t g1 = bfpack(rb[j].z, rb[j].w);
            Bhi[so[j]]     = g0;
            Bhi[so[j] + 1] = g1;
            Blo[so[j]]     = bfpack(rb[j].x - bflowf(g0), rb[j].y - bfhighf(g0));
            Blo[so[j] + 1] = bfpack(rb[j].z - bflowf(g1), rb[j].w - bfhighf(g1));
        }
        __syncthreads();

        if (kc < 31) {
            #pragma unroll
            for (int j = 0; j < 4; ++j) {
                ra[j] = pa[j][(kc + 1) * 8];
                rb[j] = pb[j][(kc + 1) * 8];
            }
        }

        #pragma unroll
        for (int ks = 0; ks < 2; ++ks) {
            const int kb = ks * 8;
            uint32_t ah[2][4], al[2][4];
            #pragma unroll
            for (int mt = 0; mt < 2; ++mt) {
                const int r0 = wm * 32 + mt * 16 + gid;
                ah[mt][0] = Ahi[r0 * SROW + kb + tig];
                ah[mt][1] = Ahi[(r0 + 8) * SROW + kb + tig];
                ah[mt][2] = Ahi[r0 * SROW + kb + tig + 4];
                ah[mt][3] = Ahi[(r0 + 8) * SROW + kb + tig + 4];
                al[mt][0] = Alo[r0 * SROW + kb + tig];
                al[mt][1] = Alo[(r0 + 8) * SROW + kb + tig];
                al[mt][2] = Alo[r0 * SROW + kb + tig + 4];
                al[mt][3] = Alo[(r0 + 8) * SROW + kb + tig + 4];
            }
            #pragma unroll
            for (int nt = 0; nt < 8; ++nt) {
                const int n = wn * 64 + nt * 8 + gid;
                uint32_t bh0 = Bhi[n * SROW + kb + tig];
                uint32_t bh1 = Bhi[n * SROW + kb + tig + 4];
                uint32_t bl0 = Blo[n * SROW + kb + tig];
                uint32_t bl1 = Blo[n * SROW + kb + tig + 4];
                #pragma unroll
                for (int mt = 0; mt < 2; ++mt) {
                    mma_bf16(acc[mt][nt], ah[mt], bh0, bh1);
                    mma_bf16(acc[mt][nt], ah[mt], bl0, bl1);
                    mma_bf16(acc[mt][nt], al[mt], bh0, bh1);
                }
            }
        }
    }

    // ---- epilogue ----
    #pragma unroll
    for (int mt = 0; mt < 2; ++mt) {
        const int row = m0 + wm * 32 + mt * 16 + gid;
        #pragma unroll
        for (int nt = 0; nt < 8; ++nt) {
            const int col = n0 + wn * 64 + nt * 8 + 2 * tig;
            const float* d = acc[mt][nt];
            if (mode == 3) {
                float2 bv = *(const float2*)(bias + col);
                *(float2*)(Cout + (size_t)row * Eq + col) =
                    make_float2(d[0] + bv.x, d[1] + bv.y);
                *(float2*)(Cout + (size_t)(row + 8) * Eq + col) =
                    make_float2(d[2] + bv.x, d[3] + bv.y);
            } else if (mode == 1) {
                const int s  = col;
                const int bb = s >> 11, sl = s & (Sq - 1);
                {
                    const int i = row, h = i >> 6, dd = i & 63;
                    const float fb = bias[i], tv = ts[h];
                    *(float2*)(g_Kt + ((size_t)(bb * Hq + h) * Dq + dd) * Sq + sl) =
                        make_float2((d[0] + fb) * tv, (d[1] + fb) * tv);
                }
                {
                    const int i = row + 8, h = i >> 6, dd = i & 63;
                    const float fb = bias[i], tv = ts[h];
                    *(float2*)(g_Kt + ((size_t)(bb * Hq + h) * Dq + dd) * Sq + sl) =
                        make_float2((d[2] + fb) * tv, (d[3] + fb) * tv);
                }
            } else {
                const int bb = row >> 11, s = row & (Sq - 1);
                const int h = col >> 6, dd = col & 63;
                float* base = (mode == 0) ? g_Q : g_V;
                float2 bv = *(const float2*)(bias + col);
                float* dst = base + ((size_t)(bb * Hq + h) * Sq + s) * Dq + dd;
                *(float2*)(dst)           = make_float2(d[0] + bv.x, d[1] + bv.y);
                *(float2*)(dst + 8 * Dq)  = make_float2(d[2] + bv.x, d[3] + bv.y);
            }
        }
    }
}

// ---------------------------------------------------------------------------
// Fused attention v3 (scalar FMA, 512 threads): one block = 16 rows of (b,h).
// Smem (floats):
//   scT [2048][18]   scores/probs (s-major)       147,456 B
//   KV  [16384]      K chunk (64d x 256s) / V chunks / hist(16x256 u32) alias
//   Qt  [64][16]     Q transposed
//   inv [16]
// red (PV partials, 4x16x64) aliases scT after PV reads complete.
// ---------------------------------------------------------------------------
#define OFF_KV   (Sq * SCPAD)            // 36864
#define OFF_QT   (OFF_KV + 16384)        // 53248
#define OFF_INV  (OFF_QT + 1024)         // 54272
#define SMEM_FLOATS (OFF_INV + 16)       // 54288 -> 217,152 B

__global__ __launch_bounds__(512, 1) void attn_kernel()
{
    extern __shared__ float smem[];
    float*    scT  = smem;
    float*    KV   = smem + OFF_KV;
    float*    Qt   = smem + OFF_QT;
    unsigned* hist = (unsigned*)KV;       // alias (middle phase only)
    float*    inv  = smem + OFF_INV;
    float*    red  = smem;                // alias (after PV reads complete)

    const int tid = threadIdx.x;
    const int bh  = blockIdx.y;
    const int t0  = blockIdx.x * TM;
    const int b   = bh >> 4;
    const int h   = bh & 15;

    const float* Qg  = g_Q  + (size_t)bh * Sq * Dq;
    const float* Ktg = g_Kt + (size_t)bh * Dq * Sq;
    const float* Vg  = g_V  + (size_t)bh * Sq * Dq;

    // ---- load Q tile transposed: Qt[d][r] ----
    for (int i = tid; i < TM * Dq; i += 512) {
        int r = i >> 6, d = i & 63;
        Qt[d * TM + r] = Qg[(size_t)(t0 + r) * Dq + d];
    }

    // ---- QK^T: 8 chunks of 256 s; per-thread 2 rows x 4 s ----
    const int tx = tid & 63;    // s-quad within chunk
    const int ty = tid >> 6;    // row pair (0..7)
    const float4* Ktg4 = (const float4*)Ktg;

    for (int c = 0; c < 8; ++c) {
        const int s0 = c * 256;
        __syncthreads();
        for (int i = tid; i < 4096; i += 512) {
            int d = i >> 6, sq = i & 63;
            ((float4*)KV)[i] = Ktg4[(size_t)d * (Sq / 4) + (s0 >> 2) + sq];
        }
        __syncthreads();

        float acc[2][4];
        #pragma unroll
        for (int i = 0; i < 2; ++i)
            #pragma unroll
            for (int j = 0; j < 4; ++j) acc[i][j] = 0.0f;

        #pragma unroll 8
        for (int d = 0; d < Dq; ++d) {
            float2 a = *(const float2*)(Qt + d * TM + ty * 2);
            float4 bb = *(const float4*)(KV + d * 256 + tx * 4);
            acc[0][0] = fmaf(a.x, bb.x, acc[0][0]); acc[0][1] = fmaf(a.x, bb.y, acc[0][1]);
            acc[0][2] = fmaf(a.x, bb.z, acc[0][2]); acc[0][3] = fmaf(a.x, bb.w, acc[0][3]);
            acc[1][0] = fmaf(a.y, bb.x, acc[1][0]); acc[1][1] = fmaf(a.y, bb.y, acc[1][1]);
            acc[1][2] = fmaf(a.y, bb.z, acc[1][2]); acc[1][3] = fmaf(a.y, bb.w, acc[1][3]);
        }

        #pragma unroll
        for (int i = 0; i < 2; ++i) {
            int r  = ty * 2 + i;
            int tg = t0 + r;
            #pragma unroll
            for (int j = 0; j < 4; ++j) {
                int s = s0 + tx * 4 + j;
                float v = acc[i][j] * SCOREMUL;
                if (s == tg) v *= DIAGMUL;
                scT[s * SCPAD + r] = v;
            }
        }
    }
    __syncthreads();

    // ---- per-row (one warp per row): exact top-k radix select + softmax ----
    {
        const int warp = tid >> 5, lane = tid & 31;
        const int r = warp;                  // 16 warps, 16 rows
        unsigned* hw = hist + warp * 256;

        unsigned thrp = 0;
        int kneed = KKq;

        for (int shift = 24; shift >= 0; shift -= 8) {
            #pragma unroll
            for (int j = 0; j < 8; ++j) hw[lane + j * 32] = 0;
            __syncwarp();
            for (int i = lane; i < Sq; i += 32) {
                unsigned u = fmap(scT[i * SCPAD + r]);
                bool ok = (shift == 24) || (((u ^ thrp) >> (shift + 8)) == 0);
                if (ok) atomicAdd(&hw[(u >> shift) & 255], 1u);
            }
            __syncwarp();
            const int b0 = (31 - lane) * 8;
            unsigned cb[8], cl = 0;
            #pragma unroll
            for (int j = 0; j < 8; ++j) { cb[j] = hw[b0 + j]; cl += cb[j]; }
            unsigned S = cl;
            #pragma unroll
            for (int o = 1; o < 32; o <<= 1) {
                unsigned x = __shfl_up_sync(0xFFFFFFFFu, S, o);
                if (lane >= o) S += x;
            }
            unsigned excl = S - cl;
            bool has = (excl < (unsigned)kneed) && ((unsigned)kneed <= S);
            unsigned bal = __ballot_sync(0xFFFFFFFFu, has);
            int src = __ffs(bal) - 1;
            int bsel = 0, nk = 0;
            if (lane == src) {
                int rem = kneed - (int)excl;
                #pragma unroll
                for (int j = 7; j >= 0; --j) {
                    int cnt = (int)cb[j];
                    if (rem <= cnt) { bsel = b0 + j; nk = rem; break; }
                    rem -= cnt;
                }
            }
            bsel  = __shfl_sync(0xFFFFFFFFu, bsel, src);
            nk    = __shfl_sync(0xFFFFFFFFu, nk, src);
            thrp |= ((unsigned)bsel) << shift;
            kneed = nk;
            __syncwarp();
        }

        // boost + row max
        float mx = -3.402823466e+38f;
        for (int i = lane; i < Sq; i += 32) {
            float v = scT[i * SCPAD + r];
            if (fmap(v) >= thrp) v *= MASKMUL;
            scT[i * SCPAD + r] = v;
            mx = fmaxf(mx, v);
        }
        #pragma unroll
        for (int o = 16; o; o >>= 1) mx = fmaxf(mx, __shfl_xor_sync(0xFFFFFFFFu, mx, o));

        // exp + sum
        float sum = 0.0f;
        for (int i = lane; i < Sq; i += 32) {
            float e = __expf(scT[i * SCPAD + r] - mx);
            scT[i * SCPAD + r] = e;
            sum += e;
        }
        #pragma unroll
        for (int o = 16; o; o >>= 1) sum += __shfl_xor_sync(0xFFFFFFFFu, sum, o);
        if (lane == 0) inv[r] = 1.0f / sum;
    }
    __syncthreads();

    // ---- P @ V: 4-way s-split; per iteration stage 256 s (4 x 64-s slices) ----
    {
        const int g  = tid >> 7;          // s quarter (0..3)
        const int rm = tid & 127;
        const int dx = rm & 15;           // d quad
        const int ry = rm >> 4;           // row pair (0..7)
        const float4* Vg4 = (const float4*)Vg;

        float4 acc0 = make_float4(0.f, 0.f, 0.f, 0.f);
        float4 acc1 = make_float4(0.f, 0.f, 0.f, 0.f);

        for (int it = 0; it < 8; ++it) {
            __syncthreads();
            // stage: KV slot q (0..255) holds global s = (q>>6)*512 + it*64 + (q&63)
            for (int i = tid; i < 4096; i += 512) {
                int q  = i >> 4, dq = i & 15;
                int s  = (q >> 6) * 512 + it * 64 + (q & 63);
                ((float4*)KV)[i] = Vg4[(size_t)s * 16 + dq];
            }
            __syncthreads();

            const int sg0 = g * 512 + it * 64;     // global s base for this quarter
            const int qb  = g * 64;                // KV slot base
            #pragma unroll 8
            for (int ls = 0; ls < 64; ++ls) {
                float2 w = *(const float2*)(scT + (sg0 + ls) * SCPAD + ry * 2);
                float4 v = *(const float4*)(KV + (qb + ls) * 64 + dx * 4);
                acc0.x = fmaf(w.x, v.x, acc0.x); acc0.y = fmaf(w.x, v.y, acc0.y);
                acc0.z = fmaf(w.x, v.z, acc0.z); acc0.w = fmaf(w.x, v.w, acc0.w);
                acc1.x = fmaf(w.y, v.x, acc1.x); acc1.y = fmaf(w.y, v.y, acc1.y);
                acc1.z = fmaf(w.y, v.z, acc1.z); acc1.w = fmaf(w.y, v.w, acc1.w);
            }
        }
        __syncthreads();   // all PV reads of scT done -> safe to alias as red
        *(float4*)(red + ((g * TM + ry * 2 + 0) * Dq + dx * 4)) = acc0;
        *(float4*)(red + ((g * TM + ry * 2 + 1) * Dq + dx * 4)) = acc1;
    }
    __syncthreads();

    // ---- reduce 4 partials, normalize, write g_O ----
    for (int i = tid; i < TM * Dq; i += 512) {
        int r = i >> 6, d = i & 63;
        float o = red[r * Dq + d] + red[(TM + r) * Dq + d]
                + red[(2 * TM + r) * Dq + d] + red[(3 * TM + r) * Dq + d];
        g_O[((size_t)(b * Sq + t0 + r)) * Eq + h * Dq + d] = o * inv[r];
    }
}

// ---------------------------------------------------------------------------
// Launch
// ---------------------------------------------------------------------------
extern "C" void kernel_launch(void* const* d_in, const int* in_sizes, int n_in,
                              void* d_out, int out_size)
{
    const float* query = (const float*)d_in[0];
    const float* key   = (const float*)d_in[1];
    const float* value = (const float*)d_in[2];
    const float* Wq    = (const float*)d_in[3];
    const float* bq    = (const float*)d_in[4];
    const float* Wk    = (const float*)d_in[5];
    const float* bk    = (const float*)d_in[6];
    const float* Wv    = (const float*)d_in[7];
    const float* bv    = (const float*)d_in[8];
    const float* Wo    = (const float*)d_in[9];
    const float* bo    = (const float*)d_in[10];
    const float* ts    = (const float*)d_in[11];

    cudaFuncSetAttribute(attn_kernel, cudaFuncAttributeMaxDynamicSharedMemorySize,
                         SMEM_FLOATS * 4);

    dim3 gT(Eq / 32, Eq / 32, 4);
    wtrans_kernel<<<gT, dim3(32, 8)>>>(Wq, Wk, Wv, Wo);

    float* wt; cudaGetSymbolAddress((void**)&wt, g_Wt);
    float* gO; cudaGetSymbolAddress((void**)&gO, g_O);

    dim3 gA(Eq / 128, (Bq * Sq) / 128);        // modes 0, 2, 3
    dim3 gK((Bq * Sq) / 128, Eq / 128);        // mode 1

    gemm_mma_kernel<<<gA, 256>>>(query, wt + 0 * (size_t)Eq * Eq, bq, ts, 0, nullptr);
    gemm_mma_kernel<<<gK, 256>>>(wt + 1 * (size_t)Eq * Eq, key,   bk, ts, 1, nullptr);
    gemm_mma_kernel<<<gA, 256>>>(value, wt + 2 * (size_t)Eq * Eq, bv, ts, 2, nullptr);

    dim3 gAttn(Sq / TM, Bq * Hq);
    attn_kernel<<<gAttn, 512, SMEM_FLOATS * 4>>>();

    gemm_mma_kernel<<<gA, 256>>>(gO, wt + 3 * (size_t)Eq * Eq, bo, ts, 3, (float*)d_out);
}

// round 7
// speedup vs baseline: 2.0609x; 1.3984x over previous
#include <cuda_runtime.h>
#include <cstdint>

// Problem constants
#define Bq 2
#define Sq 2048
#define Eq 1024
#define Hq 16
#define Dq 64
#define KKq 409           // max(1, int(S*0.2))
#define SCOREMUL 0.15625f // (1/sqrt(64)) / temperature, temperature = 0.8
#define DIAGMUL  1.15f    // 1 + ACH*0.3
#define MASKMUL  1.15f    // 1 + (-DA)*0.3

#define TM 16             // query rows per attention block
#define RS 2052           // sc row stride (floats), even, 8B-aligned rows

// ---------------------------------------------------------------------------
// Scratch (device globals)
// ---------------------------------------------------------------------------
__device__ float    g_Q [Bq*Hq*Sq*Dq];   // (b,h,s,d)
__device__ float    g_K [Bq*Hq*Sq*Dq];   // (b,h,s,d), pre-scaled by time_scales
__device__ float    g_V [Bq*Hq*Sq*Dq];   // (b,h,s,d)
__device__ float    g_O [Bq*Sq*Eq];      // (b,s,e)
__device__ float    g_Wt[4*Eq*Eq];       // Wq^T, Wk^T, Wv^T, Wo^T
__device__ uint32_t g_Kbh[Bq*Hq*Sq*32];  // K bf16 hi, (bh, s, d2)  d-pairs
__device__ uint32_t g_Kbl[Bq*Hq*Sq*32];  // K bf16 lo
__device__ uint32_t g_Vbh[Bq*Hq*Dq*1024];// V bf16 hi, (bh, d, s2)  s-pairs
__device__ uint32_t g_Vbl[Bq*Hq*Dq*1024];// V bf16 lo

// ---------------------------------------------------------------------------
// bf16x2 helpers
// ---------------------------------------------------------------------------
__device__ __forceinline__ uint32_t bfpack(float lo, float hi) {
    uint32_t r;
    asm("cvt.rn.bf16x2.f32 %0, %1, %2;" : "=r"(r) : "f"(hi), "f"(lo));
    return r;
}
__device__ __forceinline__ float bflowf(uint32_t p)  { return __uint_as_float(p << 16); }
__device__ __forceinline__ float bfhighf(uint32_t p) { return __uint_as_float(p & 0xFFFF0000u); }

__device__ __forceinline__ void mma_bf16(float* d, const uint32_t* a, uint32_t b0, uint32_t b1) {
    asm volatile(
        "mma.sync.aligned.m16n8k16.row.col.f32.bf16.bf16.f32 "
        "{%0,%1,%2,%3}, {%4,%5,%6,%7}, {%8,%9}, {%0,%1,%2,%3};"
        : "+f"(d[0]), "+f"(d[1]), "+f"(d[2]), "+f"(d[3])
        : "r"(a[0]), "r"(a[1]), "r"(a[2]), "r"(a[3]), "r"(b0), "r"(b1));
}

__device__ __forceinline__ unsigned fmap(float f) {
    unsigned u = __float_as_uint(f);
    return (u & 0x80000000u) ? ~u : (u | 0x80000000u);
}

// ---------------------------------------------------------------------------
// Weight transpose: g_Wt[z] = W(z)^T
// ---------------------------------------------------------------------------
__global__ void wtrans_kernel(const float* __restrict__ Wq, const float* __restrict__ Wk,
                              const float* __restrict__ Wv, const float* __restrict__ Wo)
{
    __shared__ float t[32][33];
    const int z = blockIdx.z;
    const float* W = (z == 0) ? Wq : (z == 1) ? Wk : (z == 2) ? Wv : Wo;
    float* out = g_Wt + (size_t)z * Eq * Eq;
    const int x0 = blockIdx.x * 32, y0 = blockIdx.y * 32;
    const int tx = threadIdx.x, ty = threadIdx.y;
    #pragma unroll
    for (int i = 0; i < 32; i += 8)
        t[ty + i][tx] = W[(size_t)(y0 + ty + i) * Eq + x0 + tx];
    __syncthreads();
    #pragma unroll
    for (int i = 0; i < 32; i += 8)
        out[(size_t)(x0 + ty + i) * Eq + y0 + tx] = t[tx][ty + i];
}

// ---------------------------------------------------------------------------
// Convert K, V fp32 -> bf16 hi/lo fragment-friendly layouts
//   z=0: K (bh, s, d2)  pairs along d
//   z=1: V (bh, d, s2)  pairs along s
// ---------------------------------------------------------------------------
__global__ __launch_bounds__(256) void conv_kernel()
{
    const int i = blockIdx.x * 256 + threadIdx.x;   // 0 .. 2M-1
    if (blockIdx.y == 0) {
        const int bh = i >> 16, rem = i & 65535;
        const int s = rem >> 5, d2 = rem & 31;
        float2 kv = *(const float2*)(g_K + (((size_t)(bh << 11) + s) << 6) + (d2 << 1));
        uint32_t hh = bfpack(kv.x, kv.y);
        g_Kbh[i] = hh;
        g_Kbl[i] = bfpack(kv.x - bflowf(hh), kv.y - bfhighf(hh));
    } else {
        const int bh = i >> 16, rem = i & 65535;
        const int d = rem >> 10, s2 = rem & 1023;
        float v0 = g_V[(((size_t)(bh << 11) + 2 * s2)     << 6) + d];
        float v1 = g_V[(((size_t)(bh << 11) + 2 * s2 + 1) << 6) + d];
        uint32_t hh = bfpack(v0, v1);
        g_Vbh[i] = hh;
        g_Vbl[i] = bfpack(v0 - bflowf(hh), v1 - bfhighf(hh));
    }
}

// ---------------------------------------------------------------------------
// bf16x3 mma.sync GEMM (validated R4/R5): C[m][n] = sum_k A[m][k]*Bt[n][k]
//   mode 0: A=query, Bt=Wq^T -> g_Q (b,h,s,d), +bq
//   mode 1: A=key,   Bt=Wk^T -> g_K (b,h,s,d), (+bk)*ts[h]
//   mode 2: A=value, Bt=Wv^T -> g_V (b,h,s,d), +bv
//   mode 3: A=g_O,   Bt=Wo^T -> Cout row-major, +bo
// ---------------------------------------------------------------------------
#define SROW 20

__global__ __launch_bounds__(256) void gemm_mma_kernel(
    const float* __restrict__ A, const float* __restrict__ Bt,
    const float* __restrict__ bias, const float* __restrict__ ts,
    int mode, float* __restrict__ Cout)
{
    __shared__ uint32_t sb[4 * 128 * SROW];
    uint32_t* Ahi = sb;
    uint32_t* Alo = sb + 128 * SROW;
    uint32_t* Bhi = sb + 2 * 128 * SROW;
    uint32_t* Blo = sb + 3 * 128 * SROW;

    const int tid  = threadIdx.x;
    const int wid  = tid >> 5, lane = tid & 31;
    const int gid  = lane >> 2, tig = lane & 3;
    const int wm   = wid & 3,  wn  = wid >> 2;
    const int m0   = blockIdx.y * 128, n0 = blockIdx.x * 128;

    const float4* pa[4];
    const float4* pb[4];
    int so[4];
    #pragma unroll
    for (int j = 0; j < 4; ++j) {
        int f4  = tid + j * 256;
        int row = f4 >> 3;
        int cq  = f4 & 7;
        pa[j] = (const float4*)(A  + (size_t)(m0 + row) * Eq) + cq;
        pb[j] = (const float4*)(Bt + (size_t)(n0 + row) * Eq) + cq;
        so[j] = row * SROW + cq * 2;
    }

    float4 ra[4], rb[4];
    #pragma unroll
    for (int j = 0; j < 4; ++j) { ra[j] = pa[j][0]; rb[j] = pb[j][0]; }

    float acc[2][8][4];
    #pragma unroll
    for (int mt = 0; mt < 2; ++mt)
        #pragma unroll
        for (int nt = 0; nt < 8; ++nt)
            #pragma unroll
            for (int c = 0; c < 4; ++c) acc[mt][nt][c] = 0.0f;

    for (int kc = 0; kc < 32; ++kc) {
        __syncthreads();
        #pragma unroll
        for (int j = 0; j < 4; ++j) {
            uint32_t h0 = bfpack(ra[j].x, ra[j].y);
            uint32_t h1 = bfpack(ra[j].z, ra[j].w);
            Ahi[so[j]]     = h0;
            Ahi[so[j] + 1] = h1;
            Alo[so[j]]     = bfpack(ra[j].x - bflowf(h0), ra[j].y - bfhighf(h0));
            Alo[so[j] + 1] = bfpack(ra[j].z - bflowf(h1), ra[j].w - bfhighf(h1));
            uint32_t g0 = bfpack(rb[j].x, rb[j].y);
            uint32_t g1 = bfpack(rb[j].z, rb[j].w);
            Bhi[so[j]]     = g0;
            Bhi[so[j] + 1] = g1;
            Blo[so[j]]     = bfpack(rb[j].x - bflowf(g0), rb[j].y - bfhighf(g0));
            Blo[so[j] + 1] = bfpack(rb[j].z - bflowf(g1), rb[j].w - bfhighf(g1));
        }
        __syncthreads();

        if (kc < 31) {
            #pragma unroll
            for (int j = 0; j < 4; ++j) {
                ra[j] = pa[j][(kc + 1) * 8];
                rb[j] = pb[j][(kc + 1) * 8];
            }
        }

        #pragma unroll
        for (int ks = 0; ks < 2; ++ks) {
            const int kb = ks * 8;
            uint32_t ah[2][4], al[2][4];
            #pragma unroll
            for (int mt = 0; mt < 2; ++mt) {
                const int r0 = wm * 32 + mt * 16 + gid;
                ah[mt][0] = Ahi[r0 * SROW + kb + tig];
                ah[mt][1] = Ahi[(r0 + 8) * SROW + kb + tig];
                ah[mt][2] = Ahi[r0 * SROW + kb + tig + 4];
                ah[mt][3] = Ahi[(r0 + 8) * SROW + kb + tig + 4];
                al[mt][0] = Alo[r0 * SROW + kb + tig];
                al[mt][1] = Alo[(r0 + 8) * SROW + kb + tig];
                al[mt][2] = Alo[r0 * SROW + kb + tig + 4];
                al[mt][3] = Alo[(r0 + 8) * SROW + kb + tig + 4];
            }
            #pragma unroll
            for (int nt = 0; nt < 8; ++nt) {
                const int n = wn * 64 + nt * 8 + gid;
                uint32_t bh0 = Bhi[n * SROW + kb + tig];
                uint32_t bh1 = Bhi[n * SROW + kb + tig + 4];
                uint32_t bl0 = Blo[n * SROW + kb + tig];
                uint32_t bl1 = Blo[n * SROW + kb + tig + 4];
                #pragma unroll
                for (int mt = 0; mt < 2; ++mt) {
                    mma_bf16(acc[mt][nt], ah[mt], bh0, bh1);
                    mma_bf16(acc[mt][nt], ah[mt], bl0, bl1);
                    mma_bf16(acc[mt][nt], al[mt], bh0, bh1);
                }
            }
        }
    }

    #pragma unroll
    for (int mt = 0; mt < 2; ++mt) {
        const int row = m0 + wm * 32 + mt * 16 + gid;
        #pragma unroll
        for (int nt = 0; nt < 8; ++nt) {
            const int col = n0 + wn * 64 + nt * 8 + 2 * tig;
            const float* d = acc[mt][nt];
            if (mode == 3) {
                float2 bv = *(const float2*)(bias + col);
                *(float2*)(Cout + (size_t)row * Eq + col) =
                    make_float2(d[0] + bv.x, d[1] + bv.y);
                *(float2*)(Cout + (size_t)(row + 8) * Eq + col) =
                    make_float2(d[2] + bv.x, d[3] + bv.y);
            } else {
                const int bb = row >> 11, s = row & (Sq - 1);
                const int h = col >> 6, dd = col & 63;
                float* base = (mode == 0) ? g_Q : (mode == 1) ? g_K : g_V;
                const float sc = (mode == 1) ? ts[h] : 1.0f;
                float2 bv = *(const float2*)(bias + col);
                float* dst = base + ((size_t)(bb * Hq + h) * Sq + s) * Dq + dd;
                *(float2*)(dst)          = make_float2((d[0] + bv.x) * sc, (d[1] + bv.y) * sc);
                *(float2*)(dst + 8 * Dq) = make_float2((d[2] + bv.x) * sc, (d[3] + bv.y) * sc);
            }
        }
    }
}

// ---------------------------------------------------------------------------
// Fused attention v4 (mma.sync, pre-converted bf16 K/V, 512 threads)
// one block = 16 query rows of one (b,h).
// Smem (floats):
//   sc  [16][2052]                  scores/probs row-major    131,328 B
//   ST  hi/lo u32 stage (2x9216)    K: [256][36], V: [64][132] 73,728 B
//        (hist 16x256 aliases stage during middle phase)
//   Qs  [16][66], inv[16]
// red (PV partials 2x16x64) aliases sc after PV reads complete.
// ---------------------------------------------------------------------------
#define OFF_ST   (TM * RS)               // 32832 floats
#define OFF_Q    (OFF_ST + 18432)        // 51264
#define OFF_INV  (OFF_Q + 16*66)         // 52320
#define SMEM_FLOATS (OFF_INV + 16)       // 52336 -> 209,344 B

__global__ __launch_bounds__(512, 1) void attn_kernel()
{
    extern __shared__ float smem[];
    float*    sc   = smem;
    uint32_t* SThi = (uint32_t*)(smem + OFF_ST);
    uint32_t* STlo = SThi + 9216;
    float*    Qs   = smem + OFF_Q;
    unsigned* hist = (unsigned*)(smem + OFF_ST);   // alias (middle only)
    float*    inv  = smem + OFF_INV;
    float*    red  = smem;                         // alias (after PV reads)

    const int tid = threadIdx.x;
    const int w   = tid >> 5, lane = tid & 31;
    const int gid = lane >> 2, tig = lane & 3;
    const int bh  = blockIdx.y;
    const int t0  = blockIdx.x * TM;
    const int b   = bh >> 4, h = bh & 15;

    const float* Qg = g_Q + (size_t)bh * Sq * Dq;

    // ---- Q stage + A fragments ----
    for (int i = tid; i < TM * Dq; i += 512) {
        int r = i >> 6, d = i & 63;
        Qs[r * 66 + d] = Qg[(size_t)(t0 + r) * Dq + d];
    }
    __syncthreads();

    uint32_t ahq[4][4], alq[4][4];
    #pragma unroll
    for (int ks = 0; ks < 4; ++ks) {
        float2 q[4];
        q[0] = *(float2*)&Qs[gid * 66 + ks * 16 + 2 * tig];
        q[1] = *(float2*)&Qs[(gid + 8) * 66 + ks * 16 + 2 * tig];
        q[2] = *(float2*)&Qs[gid * 66 + ks * 16 + 2 * tig + 8];
        q[3] = *(float2*)&Qs[(gid + 8) * 66 + ks * 16 + 2 * tig + 8];
        #pragma unroll
        for (int j = 0; j < 4; ++j) {
            uint32_t hh = bfpack(q[j].x, q[j].y);
            ahq[ks][j] = hh;
            alq[ks][j] = bfpack(q[j].x - bflowf(hh), q[j].y - bfhighf(hh));
        }
    }

    // ---- QK^T: 8 chunks of 256 s, pure-copy bf16 staging ----
    const uint32_t* Kbh = g_Kbh + ((size_t)bh << 16);
    const uint32_t* Kbl = g_Kbl + ((size_t)bh << 16);

    for (int c = 0; c < 8; ++c) {
        __syncthreads();
        #pragma unroll
        for (int k = 0; k < 8; ++k) {
            int j = tid + k * 512;            // 0..4095 uint4 slots
            int arr = j >> 11, jj = j & 2047;
            int s = jj >> 3, q = jj & 7;
            const uint4* src = (const uint4*)(arr ? Kbl : Kbh);
            uint4 v = src[(((c << 8) + s) << 3) + q];
            uint32_t* dst = arr ? STlo : SThi;
            *(uint4*)(dst + s * 36 + q * 4) = v;
        }
        __syncthreads();

        #pragma unroll
        for (int nt = 0; nt < 2; ++nt) {
            const int sl = w * 16 + nt * 8 + gid;
            float cf[4] = {0.f, 0.f, 0.f, 0.f};
            #pragma unroll
            for (int ks = 0; ks < 4; ++ks) {
                uint32_t b0h = SThi[sl * 36 + ks * 8 + tig];
                uint32_t b1h = SThi[sl * 36 + ks * 8 + 4 + tig];
                uint32_t b0l = STlo[sl * 36 + ks * 8 + tig];
                uint32_t b1l = STlo[sl * 36 + ks * 8 + 4 + tig];
                mma_bf16(cf, ahq[ks], b0h, b1h);
                mma_bf16(cf, ahq[ks], b0l, b1l);
                mma_bf16(cf, alq[ks], b0h, b1h);
            }
            const int sg = (c << 8) + w * 16 + nt * 8 + 2 * tig;
            float v0 = cf[0] * SCOREMUL; if (sg     == t0 + gid)     v0 *= DIAGMUL;
            float v1 = cf[1] * SCOREMUL; if (sg + 1 == t0 + gid)     v1 *= DIAGMUL;
            float v2 = cf[2] * SCOREMUL; if (sg     == t0 + gid + 8) v2 *= DIAGMUL;
            float v3 = cf[3] * SCOREMUL; if (sg + 1 == t0 + gid + 8) v3 *= DIAGMUL;
            *(float2*)&sc[gid * RS + sg]       = make_float2(v0, v1);
            *(float2*)&sc[(gid + 8) * RS + sg] = make_float2(v2, v3);
        }
    }
    __syncthreads();

    // ---- per-row (one warp per row): exact top-k radix select + softmax ----
    {
        const int r = w;
        unsigned* hw = hist + w * 256;

        unsigned thrp = 0;
        int kneed = KKq;

        for (int shift = 24; shift >= 0; shift -= 8) {
            #pragma unroll
            for (int j = 0; j < 8; ++j) hw[lane + j * 32] = 0;
            __syncwarp();
            for (int i = lane; i < Sq; i += 32) {
                unsigned u = fmap(sc[r * RS + i]);
                bool ok = (shift == 24) || (((u ^ thrp) >> (shift + 8)) == 0);
                if (ok) atomicAdd(&hw[(u >> shift) & 255], 1u);
            }
            __syncwarp();
            const int b0 = (31 - lane) * 8;
            unsigned cb[8], cl = 0;
            #pragma unroll
            for (int j = 0; j < 8; ++j) { cb[j] = hw[b0 + j]; cl += cb[j]; }
            unsigned S = cl;
            #pragma unroll
            for (int o = 1; o < 32; o <<= 1) {
                unsigned x = __shfl_up_sync(0xFFFFFFFFu, S, o);
                if (lane >= o) S += x;
            }
            unsigned excl = S - cl;
            bool has = (excl < (unsigned)kneed) && ((unsigned)kneed <= S);
            unsigned bal = __ballot_sync(0xFFFFFFFFu, has);
            int src = __ffs(bal) - 1;
            int bsel = 0, nk = 0;
            if (lane == src) {
                int rem = kneed - (int)excl;
                #pragma unroll
                for (int j = 7; j >= 0; --j) {
                    int cnt = (int)cb[j];
                    if (rem <= cnt) { bsel = b0 + j; nk = rem; break; }
                    rem -= cnt;
                }
            }
            bsel  = __shfl_sync(0xFFFFFFFFu, bsel, src);
            nk    = __shfl_sync(0xFFFFFFFFu, nk, src);
            thrp |= ((unsigned)bsel) << shift;
            kneed = nk;
            __syncwarp();
        }

        float mx = -3.402823466e+38f;
        for (int i = lane; i < Sq; i += 32) {
            float v = sc[r * RS + i];
            if (fmap(v) >= thrp) v *= MASKMUL;
            sc[r * RS + i] = v;
            mx = fmaxf(mx, v);
        }
        #pragma unroll
        for (int o = 16; o; o >>= 1) mx = fmaxf(mx, __shfl_xor_sync(0xFFFFFFFFu, mx, o));

        float sum = 0.0f;
        for (int i = lane; i < Sq; i += 32) {
            float e = __expf(sc[r * RS + i] - mx);
            sc[r * RS + i] = e;
            sum += e;
        }
        #pragma unroll
        for (int o = 16; o; o >>= 1) sum += __shfl_xor_sync(0xFFFFFFFFu, sum, o);
        if (lane == 0) inv[r] = 1.0f / sum;
    }

    // ---- P @ V via mma: warp -> (d-tile nd, k-half kh), accumulate 8 chunks --
    const uint32_t* Vbh = g_Vbh + ((size_t)bh << 16);
    const uint32_t* Vbl = g_Vbl + ((size_t)bh << 16);
    const int nd = w & 7, kh = w >> 3;
    float cacc[4] = {0.f, 0.f, 0.f, 0.f};

    for (int c = 0; c < 8; ++c) {
        __syncthreads();   // (first iteration also closes the middle phase)
        #pragma unroll
        for (int k = 0; k < 8; ++k) {
            int j = tid + k * 512;
            int arr = j >> 11, jj = j & 2047;
            int d = jj >> 5, q = jj & 31;
            const uint4* src = (const uint4*)(arr ? Vbl : Vbh);
            uint4 v = src[(d << 8) + (c << 5) + q];
            uint32_t* dst = arr ? STlo : SThi;
            *(uint4*)(dst + d * 132 + q * 4) = v;
        }
        __syncthreads();

        #pragma unroll
        for (int kk = 0; kk < 8; ++kk) {
            const int k0  = (c << 8) + (kh << 7) + (kk << 4);  // global s base
            const int s2b = (kh << 6) + (kk << 3);             // local s2 base
            uint32_t ah[4], al[4];
            float2 p;
            p = *(float2*)&sc[gid * RS + k0 + 2 * tig];
            ah[0] = bfpack(p.x, p.y); al[0] = bfpack(p.x - bflowf(ah[0]), p.y - bfhighf(ah[0]));
            p = *(float2*)&sc[(gid + 8) * RS + k0 + 2 * tig];
            ah[1] = bfpack(p.x, p.y); al[1] = bfpack(p.x - bflowf(ah[1]), p.y - bfhighf(ah[1]));
            p = *(float2*)&sc[gid * RS + k0 + 8 + 2 * tig];
            ah[2] = bfpack(p.x, p.y); al[2] = bfpack(p.x - bflowf(ah[2]), p.y - bfhighf(ah[2]));
            p = *(float2*)&sc[(gid + 8) * RS + k0 + 8 + 2 * tig];
            ah[3] = bfpack(p.x, p.y); al[3] = bfpack(p.x - bflowf(ah[3]), p.y - bfhighf(ah[3]));

            const int vrow = (nd * 8 + gid) * 132;
            uint32_t b0h = SThi[vrow + s2b + tig];
            uint32_t b1h = SThi[vrow + s2b + 4 + tig];
            uint32_t b0l = STlo[vrow + s2b + tig];
            uint32_t b1l = STlo[vrow + s2b + 4 + tig];
            mma_bf16(cacc, ah, b0h, b1h);
            mma_bf16(cacc, ah, b0l, b1l);
            mma_bf16(cacc, al, b0h, b1h);
        }
    }
    __syncthreads();   // all PV reads of sc done -> safe to alias as red

    *(float2*)&red[(kh << 10) + gid * 64 + nd * 8 + 2 * tig]       = make_float2(cacc[0], cacc[1]);
    *(float2*)&red[(kh << 10) + (gid + 8) * 64 + nd * 8 + 2 * tig] = make_float2(cacc[2], cacc[3]);
    __syncthreads();

    for (int i = tid; i < TM * Dq; i += 512) {
        int r = i >> 6, d = i & 63;
        float o = (red[i] + red[1024 + i]) * inv[r];
        g_O[((size_t)(b * Sq + t0 + r)) * Eq + h * Dq + d] = o;
    }
}

// ---------------------------------------------------------------------------
// Launch
// ---------------------------------------------------------------------------
extern "C" void kernel_launch(void* const* d_in, const int* in_sizes, int n_in,
                              void* d_out, int out_size)
{
    const float* query = (const float*)d_in[0];
    const float* key   = (const float*)d_in[1];
    const float* value = (const float*)d_in[2];
    const float* Wq    = (const float*)d_in[3];
    const float* bq    = (const float*)d_in[4];
    const float* Wk    = (const float*)d_in[5];
    const float* bk    = (const float*)d_in[6];
    const float* Wv    = (const float*)d_in[7];
    const float* bv    = (const float*)d_in[8];
    const float* Wo    = (const float*)d_in[9];
    const float* bo    = (const float*)d_in[10];
    const float* ts    = (const float*)d_in[11];

    cudaFuncSetAttribute(attn_kernel, cudaFuncAttributeMaxDynamicSharedMemorySize,
                         SMEM_FLOATS * 4);

    dim3 gT(Eq / 32, Eq / 32, 4);
    wtrans_kernel<<<gT, dim3(32, 8)>>>(Wq, Wk, Wv, Wo);

    float* wt; cudaGetSymbolAddress((void**)&wt, g_Wt);
    float* gO; cudaGetSymbolAddress((void**)&gO, g_O);

    dim3 gA(Eq / 128, (Bq * Sq) / 128);

    gemm_mma_kernel<<<gA, 256>>>(query, wt + 0 * (size_t)Eq * Eq, bq, ts, 0, nullptr);
    gemm_mma_kernel<<<gA, 256>>>(key,   wt + 1 * (size_t)Eq * Eq, bk, ts, 1, nullptr);
    gemm_mma_kernel<<<gA, 256>>>(value, wt + 2 * (size_t)Eq * Eq, bv, ts, 2, nullptr);

    conv_kernel<<<dim3(8192, 2), 256>>>();

    dim3 gAttn(Sq / TM, Bq * Hq);
    attn_kernel<<<gAttn, 512, SMEM_FLOATS * 4>>>();

    gemm_mma_kernel<<<gA, 256>>>(gO, wt + 3 * (size_t)Eq * Eq, bo, ts, 3, (float*)d_out);
}

// round 8
// speedup vs baseline: 2.1536x; 1.0450x over previous
#include <cuda_runtime.h>
#include <cstdint>

// Problem constants
#define Bq 2
#define Sq 2048
#define Eq 1024
#define Hq 16
#define Dq 64
#define KKq 409           // max(1, int(S*0.2))
#define SCOREMUL 0.15625f // (1/sqrt(64)) / temperature, temperature = 0.8
#define DIAGMUL  1.15f    // 1 + ACH*0.3
#define MASKMUL  1.15f    // 1 + (-DA)*0.3

#define TM 16             // query rows per attention block
#define RS 2052           // sc row stride (floats)

// ---------------------------------------------------------------------------
// Scratch (device globals)
// ---------------------------------------------------------------------------
__device__ float    g_Q [Bq*Hq*Sq*Dq];   // (b,h,s,d)
__device__ float    g_K [Bq*Hq*Sq*Dq];   // (b,h,s,d), pre-scaled by time_scales
__device__ float    g_V [Bq*Hq*Sq*Dq];   // (b,h,s,d)
__device__ float    g_O [Bq*Sq*Eq];      // (b,s,e)
__device__ float    g_Wt[4*Eq*Eq];       // Wq^T, Wk^T, Wv^T, Wo^T
__device__ uint32_t g_Kbh[Bq*Hq*Sq*32];  // K bf16 hi, (bh, s, d2)
__device__ uint32_t g_Kbl[Bq*Hq*Sq*32];  // K bf16 lo
__device__ uint32_t g_Vbh[Bq*Hq*Dq*1024];// V bf16 hi, (bh, d, s2)
__device__ uint32_t g_Vbl[Bq*Hq*Dq*1024];// V bf16 lo

// ---------------------------------------------------------------------------
// helpers
// ---------------------------------------------------------------------------
__device__ __forceinline__ uint32_t bfpack(float lo, float hi) {
    uint32_t r;
    asm("cvt.rn.bf16x2.f32 %0, %1, %2;" : "=r"(r) : "f"(hi), "f"(lo));
    return r;
}
__device__ __forceinline__ float bflowf(uint32_t p)  { return __uint_as_float(p << 16); }
__device__ __forceinline__ float bfhighf(uint32_t p) { return __uint_as_float(p & 0xFFFF0000u); }

__device__ __forceinline__ void mma_bf16(float* d, const uint32_t* a, uint32_t b0, uint32_t b1) {
    asm volatile(
        "mma.sync.aligned.m16n8k16.row.col.f32.bf16.bf16.f32 "
        "{%0,%1,%2,%3}, {%4,%5,%6,%7}, {%8,%9}, {%0,%1,%2,%3};"
        : "+f"(d[0]), "+f"(d[1]), "+f"(d[2]), "+f"(d[3])
        : "r"(a[0]), "r"(a[1]), "r"(a[2]), "r"(a[3]), "r"(b0), "r"(b1));
}

__device__ __forceinline__ unsigned fmap(float f) {
    unsigned u = __float_as_uint(f);
    return (u & 0x80000000u) ? ~u : (u | 0x80000000u);
}

__device__ __forceinline__ uint32_t smem_u32(const void* p) {
    uint32_t a;
    asm("{ .reg .u64 t; cvta.to.shared.u64 t, %1; cvt.u32.u64 %0, t; }" : "=r"(a) : "l"(p));
    return a;
}
__device__ __forceinline__ void cpa16(uint32_t dst, const void* src) {
    asm volatile("cp.async.cg.shared.global [%0], [%1], 16;" :: "r"(dst), "l"(src) : "memory");
}
#define CPA_COMMIT() asm volatile("cp.async.commit_group;" ::: "memory")
#define CPA_WAIT1()  asm volatile("cp.async.wait_group 1;" ::: "memory")
#define CPA_WAIT0()  asm volatile("cp.async.wait_group 0;" ::: "memory")

// ---------------------------------------------------------------------------
// Weight transpose: g_Wt[z] = W(z)^T
// ---------------------------------------------------------------------------
__global__ void wtrans_kernel(const float* __restrict__ Wq, const float* __restrict__ Wk,
                              const float* __restrict__ Wv, const float* __restrict__ Wo)
{
    __shared__ float t[32][33];
    const int z = blockIdx.z;
    const float* W = (z == 0) ? Wq : (z == 1) ? Wk : (z == 2) ? Wv : Wo;
    float* out = g_Wt + (size_t)z * Eq * Eq;
    const int x0 = blockIdx.x * 32, y0 = blockIdx.y * 32;
    const int tx = threadIdx.x, ty = threadIdx.y;
    #pragma unroll
    for (int i = 0; i < 32; i += 8)
        t[ty + i][tx] = W[(size_t)(y0 + ty + i) * Eq + x0 + tx];
    __syncthreads();
    #pragma unroll
    for (int i = 0; i < 32; i += 8)
        out[(size_t)(x0 + ty + i) * Eq + y0 + tx] = t[tx][ty + i];
}

// ---------------------------------------------------------------------------
// Convert K, V fp32 -> bf16 hi/lo fragment-friendly layouts
// ---------------------------------------------------------------------------
__global__ __launch_bounds__(256) void conv_kernel()
{
    const int i = blockIdx.x * 256 + threadIdx.x;
    if (blockIdx.y == 0) {
        const int bh = i >> 16, rem = i & 65535;
        const int s = rem >> 5, d2 = rem & 31;
        float2 kv = *(const float2*)(g_K + (((size_t)(bh << 11) + s) << 6) + (d2 << 1));
        uint32_t hh = bfpack(kv.x, kv.y);
        g_Kbh[i] = hh;
        g_Kbl[i] = bfpack(kv.x - bflowf(hh), kv.y - bfhighf(hh));
    } else {
        const int bh = i >> 16, rem = i & 65535;
        const int d = rem >> 10, s2 = rem & 1023;
        float v0 = g_V[(((size_t)(bh << 11) + 2 * s2)     << 6) + d];
        float v1 = g_V[(((size_t)(bh << 11) + 2 * s2 + 1) << 6) + d];
        uint32_t hh = bfpack(v0, v1);
        g_Vbh[i] = hh;
        g_Vbl[i] = bfpack(v0 - bflowf(hh), v1 - bfhighf(hh));
    }
}

// ---------------------------------------------------------------------------
// bf16x3 mma.sync GEMM (validated): C[m][n] = sum_k A[m][k]*Bt[n][k]
// ---------------------------------------------------------------------------
#define SROW 20

__global__ __launch_bounds__(256) void gemm_mma_kernel(
    const float* __restrict__ A, const float* __restrict__ Bt,
    const float* __restrict__ bias, const float* __restrict__ ts,
    int mode, float* __restrict__ Cout)
{
    __shared__ uint32_t sb[4 * 128 * SROW];
    uint32_t* Ahi = sb;
    uint32_t* Alo = sb + 128 * SROW;
    uint32_t* Bhi = sb + 2 * 128 * SROW;
    uint32_t* Blo = sb + 3 * 128 * SROW;

    const int tid  = threadIdx.x;
    const int wid  = tid >> 5, lane = tid & 31;
    const int gid  = lane >> 2, tig = lane & 3;
    const int wm   = wid & 3,  wn  = wid >> 2;
    const int m0   = blockIdx.y * 128, n0 = blockIdx.x * 128;

    const float4* pa[4];
    const float4* pb[4];
    int so[4];
    #pragma unroll
    for (int j = 0; j < 4; ++j) {
        int f4  = tid + j * 256;
        int row = f4 >> 3;
        int cq  = f4 & 7;
        pa[j] = (const float4*)(A  + (size_t)(m0 + row) * Eq) + cq;
        pb[j] = (const float4*)(Bt + (size_t)(n0 + row) * Eq) + cq;
        so[j] = row * SROW + cq * 2;
    }

    float4 ra[4], rb[4];
    #pragma unroll
    for (int j = 0; j < 4; ++j) { ra[j] = pa[j][0]; rb[j] = pb[j][0]; }

    float acc[2][8][4];
    #pragma unroll
    for (int mt = 0; mt < 2; ++mt)
        #pragma unroll
        for (int nt = 0; nt < 8; ++nt)
            #pragma unroll
            for (int c = 0; c < 4; ++c) acc[mt][nt][c] = 0.0f;

    for (int kc = 0; kc < 32; ++kc) {
        __syncthreads();
        #pragma unroll
        for (int j = 0; j < 4; ++j) {
            uint32_t h0 = bfpack(ra[j].x, ra[j].y);
            uint32_t h1 = bfpack(ra[j].z, ra[j].w);
            Ahi[so[j]]     = h0;
            Ahi[so[j] + 1] = h1;
            Alo[so[j]]     = bfpack(ra[j].x - bflowf(h0), ra[j].y - bfhighf(h0));
            Alo[so[j] + 1] = bfpack(ra[j].z - bflowf(h1), ra[j].w - bfhighf(h1));
            uint32_t g0 = bfpack(rb[j].x, rb[j].y);
            uint32_t g1 = bfpack(rb[j].z, rb[j].w);
            Bhi[so[j]]     = g0;
            Bhi[so[j] + 1] = g1;
            Blo[so[j]]     = bfpack(rb[j].x - bflowf(g0), rb[j].y - bfhighf(g0));
            Blo[so[j] + 1] = bfpack(rb[j].z - bflowf(g1), rb[j].w - bfhighf(g1));
        }
        __syncthreads();

        if (kc < 31) {
            #pragma unroll
            for (int j = 0; j < 4; ++j) {
                ra[j] = pa[j][(kc + 1) * 8];
                rb[j] = pb[j][(kc + 1) * 8];
            }
        }

        #pragma unroll
        for (int ks = 0; ks < 2; ++ks) {
            const int kb = ks * 8;
            uint32_t ah[2][4], al[2][4];
            #pragma unroll
            for (int mt = 0; mt < 2; ++mt) {
                const int r0 = wm * 32 + mt * 16 + gid;
                ah[mt][0] = Ahi[r0 * SROW + kb + tig];
                ah[mt][1] = Ahi[(r0 + 8) * SROW + kb + tig];
                ah[mt][2] = Ahi[r0 * SROW + kb + tig + 4];
                ah[mt][3] = Ahi[(r0 + 8) * SROW + kb + tig + 4];
                al[mt][0] = Alo[r0 * SROW + kb + tig];
                al[mt][1] = Alo[(r0 + 8) * SROW + kb + tig];
                al[mt][2] = Alo[r0 * SROW + kb + tig + 4];
                al[mt][3] = Alo[(r0 + 8) * SROW + kb + tig + 4];
            }
            #pragma unroll
            for (int nt = 0; nt < 8; ++nt) {
                const int n = wn * 64 + nt * 8 + gid;
                uint32_t bh0 = Bhi[n * SROW + kb + tig];
                uint32_t bh1 = Bhi[n * SROW + kb + tig + 4];
                uint32_t bl0 = Blo[n * SROW + kb + tig];
                uint32_t bl1 = Blo[n * SROW + kb + tig + 4];
                #pragma unroll
                for (int mt = 0; mt < 2; ++mt) {
                    mma_bf16(acc[mt][nt], ah[mt], bh0, bh1);
                    mma_bf16(acc[mt][nt], ah[mt], bl0, bl1);
                    mma_bf16(acc[mt][nt], al[mt], bh0, bh1);
                }
            }
        }
    }

    #pragma unroll
    for (int mt = 0; mt < 2; ++mt) {
        const int row = m0 + wm * 32 + mt * 16 + gid;
        #pragma unroll
        for (int nt = 0; nt < 8; ++nt) {
            const int col = n0 + wn * 64 + nt * 8 + 2 * tig;
            const float* d = acc[mt][nt];
            if (mode == 3) {
                float2 bv = *(const float2*)(bias + col);
                *(float2*)(Cout + (size_t)row * Eq + col) =
                    make_float2(d[0] + bv.x, d[1] + bv.y);
                *(float2*)(Cout + (size_t)(row + 8) * Eq + col) =
                    make_float2(d[2] + bv.x, d[3] + bv.y);
            } else {
                const int bb = row >> 11, s = row & (Sq - 1);
                const int h = col >> 6, dd = col & 63;
                float* base = (mode == 0) ? g_Q : (mode == 1) ? g_K : g_V;
                const float sc = (mode == 1) ? ts[h] : 1.0f;
                float2 bv = *(const float2*)(bias + col);
                float* dst = base + ((size_t)(bb * Hq + h) * Sq + s) * Dq + dd;
                *(float2*)(dst)          = make_float2((d[0] + bv.x) * sc, (d[1] + bv.y) * sc);
                *(float2*)(dst + 8 * Dq) = make_float2((d[2] + bv.x) * sc, (d[3] + bv.y) * sc);
            }
        }
    }
}

// ---------------------------------------------------------------------------
// Fused attention v5 (mma + cp.async double-buffered staging, 512 threads)
// Smem (floats):
//   sc  [16][2052]   scores -> packed bf16 hi/lo probs      131,328 B
//   ST  18432 fl     K stage: 2 buf x 2 arr x [128][36]
//                    V stage: 2 buf x 2 arr x [64][68] (aliased)
//                    hist 16x256 (aliased, middle phase)
//   Qs  [16][66], inv[16]
// ---------------------------------------------------------------------------
#define OFF_ST   (TM * RS)               // 32832
#define KBUF     4608                    // 128*36 u32 per array
#define VBUF     4352                    // 64*68 u32 per array
#define OFF_Q    (OFF_ST + 18432)        // 51264
#define OFF_INV  (OFF_Q + 16*66)         // 52320
#define SMEM_FLOATS (OFF_INV + 16)       // 52336 -> 209,344 B

__global__ __launch_bounds__(512, 1) void attn_kernel()
{
    extern __shared__ float smem[];
    float*    sc     = smem;
    uint32_t* sc_u   = (uint32_t*)smem;
    uint32_t* ST     = (uint32_t*)(smem + OFF_ST);
    float*    Qs     = smem + OFF_Q;
    unsigned* hist   = (unsigned*)(smem + OFF_ST);   // alias (middle only)
    float*    inv    = smem + OFF_INV;
    float*    red    = smem;                         // alias (after PV reads)
    const uint32_t st_b = smem_u32(ST);              // byte smem address of ST

    const int tid = threadIdx.x;
    const int w   = tid >> 5, lane = tid & 31;
    const int gid = lane >> 2, tig = lane & 3;
    const int bh  = blockIdx.y;
    const int t0  = blockIdx.x * TM;
    const int b   = bh >> 4, h = bh & 15;

    const float* Qg  = g_Q + (size_t)bh * Sq * Dq;
    const uint4* Kb4[2] = { (const uint4*)(g_Kbh + ((size_t)bh << 16)),
                            (const uint4*)(g_Kbl + ((size_t)bh << 16)) };
    const uint4* Vb4[2] = { (const uint4*)(g_Vbh + ((size_t)bh << 16)),
                            (const uint4*)(g_Vbl + ((size_t)bh << 16)) };

    // staging index maps (per thread, 4 x 16B per chunk)
    int karr[4], ksl[4], kq[4], varr[4], vd[4], vq[4];
    #pragma unroll
    for (int k = 0; k < 4; ++k) {
        int idx = tid + k * 512;                 // 0..2047
        karr[k] = idx >> 10; ksl[k] = (idx & 1023) >> 3; kq[k] = idx & 7;
        varr[k] = idx >> 10; vd[k]  = (idx & 1023) >> 4; vq[k] = idx & 15;
    }

    // ---- Q stage ----
    for (int i = tid; i < TM * Dq; i += 512) {
        int r = i >> 6, d = i & 63;
        Qs[r * 66 + d] = Qg[(size_t)(t0 + r) * Dq + d];
    }

    // prefetch K chunk 0 into buf 0
    #pragma unroll
    for (int k = 0; k < 4; ++k)
        cpa16(st_b + (((karr[k]) * KBUF + ksl[k] * 36 + kq[k] * 4) << 2),
              Kb4[karr[k]] + (size_t)ksl[k] * 8 + kq[k]);
    CPA_COMMIT();
    __syncthreads();

    // ---- Q fragments ----
    uint32_t ahq[4][4], alq[4][4];
    #pragma unroll
    for (int ks = 0; ks < 4; ++ks) {
        float2 q[4];
        q[0] = *(float2*)&Qs[gid * 66 + ks * 16 + 2 * tig];
        q[1] = *(float2*)&Qs[(gid + 8) * 66 + ks * 16 + 2 * tig];
        q[2] = *(float2*)&Qs[gid * 66 + ks * 16 + 2 * tig + 8];
        q[3] = *(float2*)&Qs[(gid + 8) * 66 + ks * 16 + 2 * tig + 8];
        #pragma unroll
        for (int j = 0; j < 4; ++j) {
            uint32_t hh = bfpack(q[j].x, q[j].y);
            ahq[ks][j] = hh;
            alq[ks][j] = bfpack(q[j].x - bflowf(hh), q[j].y - bfhighf(hh));
        }
    }

    // ---- QK^T: 16 chunks of 128 s, double-buffered ----
    for (int c = 0; c < 16; ++c) {
        const int buf = c & 1;
        if (c < 15) {
            const int cn = c + 1, bn = buf ^ 1;
            #pragma unroll
            for (int k = 0; k < 4; ++k)
                cpa16(st_b + (((bn * 2 + karr[k]) * KBUF + ksl[k] * 36 + kq[k] * 4) << 2),
                      Kb4[karr[k]] + (size_t)(cn * 128 + ksl[k]) * 8 + kq[k]);
            CPA_COMMIT();
            CPA_WAIT1();
        } else {
            CPA_WAIT0();
        }
        __syncthreads();

        const uint32_t* KH = ST + buf * 2 * KBUF;
        const uint32_t* KL = KH + KBUF;
        const int sl = w * 8 + gid;
        float cf[4] = {0.f, 0.f, 0.f, 0.f};
        #pragma unroll
        for (int ks = 0; ks < 4; ++ks) {
            uint32_t b0h = KH[sl * 36 + ks * 8 + tig];
            uint32_t b1h = KH[sl * 36 + ks * 8 + 4 + tig];
            uint32_t b0l = KL[sl * 36 + ks * 8 + tig];
            uint32_t b1l = KL[sl * 36 + ks * 8 + 4 + tig];
            mma_bf16(cf, ahq[ks], b0h, b1h);
            mma_bf16(cf, ahq[ks], b0l, b1l);
            mma_bf16(cf, alq[ks], b0h, b1h);
        }
        const int sg = (c << 7) + w * 8 + 2 * tig;
        float v0 = cf[0] * SCOREMUL; if (sg     == t0 + gid)     v0 *= DIAGMUL;
        float v1 = cf[1] * SCOREMUL; if (sg + 1 == t0 + gid)     v1 *= DIAGMUL;
        float v2 = cf[2] * SCOREMUL; if (sg     == t0 + gid + 8) v2 *= DIAGMUL;
        float v3 = cf[3] * SCOREMUL; if (sg + 1 == t0 + gid + 8) v3 *= DIAGMUL;
        *(float2*)&sc[gid * RS + sg]       = make_float2(v0, v1);
        *(float2*)&sc[(gid + 8) * RS + sg] = make_float2(v2, v3);
        __syncthreads();
    }

    // ---- per-row (one warp per row): top-k radix select + softmax + pack ----
    {
        const int r = w;
        unsigned* hw = hist + w * 256;

        unsigned thrp = 0;
        int kneed = KKq;

        for (int shift = 24; shift >= 0; shift -= 8) {
            #pragma unroll
            for (int j = 0; j < 8; ++j) hw[lane + j * 32] = 0;
            __syncwarp();
            for (int i = lane; i < Sq; i += 32) {
                unsigned u = fmap(sc[r * RS + i]);
                bool ok = (shift == 24) || (((u ^ thrp) >> (shift + 8)) == 0);
                if (ok) atomicAdd(&hw[(u >> shift) & 255], 1u);
            }
            __syncwarp();
            const int b0 = (31 - lane) * 8;
            unsigned cb[8], cl = 0;
            #pragma unroll
            for (int j = 0; j < 8; ++j) { cb[j] = hw[b0 + j]; cl += cb[j]; }
            unsigned S = cl;
            #pragma unroll
            for (int o = 1; o < 32; o <<= 1) {
                unsigned x = __shfl_up_sync(0xFFFFFFFFu, S, o);
                if (lane >= o) S += x;
            }
            unsigned excl = S - cl;
            bool has = (excl < (unsigned)kneed) && ((unsigned)kneed <= S);
            unsigned bal = __ballot_sync(0xFFFFFFFFu, has);
            int src = __ffs(bal) - 1;
            int bsel = 0, nk = 0;
            if (lane == src) {
                int rem = kneed - (int)excl;
                #pragma unroll
                for (int j = 7; j >= 0; --j) {
                    int cnt = (int)cb[j];
                    if (rem <= cnt) { bsel = b0 + j; nk = rem; break; }
                    rem -= cnt;
                }
            }
            bsel  = __shfl_sync(0xFFFFFFFFu, bsel, src);
            nk    = __shfl_sync(0xFFFFFFFFu, nk, src);
            thrp |= ((unsigned)bsel) << shift;
            kneed = nk;
            __syncwarp();
        }

        // boost + row max
        float mx = -3.402823466e+38f;
        for (int i = lane; i < Sq; i += 32) {
            float v = sc[r * RS + i];
            if (fmap(v) >= thrp) v *= MASKMUL;
            sc[r * RS + i] = v;
            mx = fmaxf(mx, v);
        }
        #pragma unroll
        for (int o = 16; o; o >>= 1) mx = fmaxf(mx, __shfl_xor_sync(0xFFFFFFFFu, mx, o));

        // exp + sum + pack to bf16 hi/lo (in place, pairwise)
        float sum = 0.0f;
        #pragma unroll 4
        for (int j = 0; j < 32; ++j) {
            const int p = lane + 32 * j;
            float2 v = *(float2*)&sc[r * RS + 2 * p];
            float e0 = __expf(v.x - mx);
            float e1 = __expf(v.y - mx);
            sum += e0 + e1;
            uint32_t hh = bfpack(e0, e1);
            uint32_t ll = bfpack(e0 - bflowf(hh), e1 - bfhighf(hh));
            uint2 pk; pk.x = hh; pk.y = ll;
            *(uint2*)&sc_u[r * RS + 2 * p] = pk;
        }
        #pragma unroll
        for (int o = 16; o; o >>= 1) sum += __shfl_xor_sync(0xFFFFFFFFu, sum, o);
        if (lane == 0) inv[r] = 1.0f / sum;
    }
    __syncthreads();   // hists/packing done; ST region free for V staging

    // ---- P @ V: 16 chunks of 128 s, double-buffered; warp=(kh, nd) ----
    const int nd = w & 7, kh = w >> 3;
    float cacc[4] = {0.f, 0.f, 0.f, 0.f};

    // prefetch V chunk 0 into buf 0
    #pragma unroll
    for (int k = 0; k < 4; ++k)
        cpa16(st_b + (((varr[k]) * VBUF + vd[k] * 68 + vq[k] * 4) << 2),
              Vb4[varr[k]] + (size_t)vd[k] * 256 + vq[k]);
    CPA_COMMIT();

    for (int c = 0; c < 16; ++c) {
        const int buf = c & 1;
        if (c < 15) {
            const int cn = c + 1, bn = buf ^ 1;
            #pragma unroll
            for (int k = 0; k < 4; ++k)
                cpa16(st_b + (((bn * 2 + varr[k]) * VBUF + vd[k] * 68 + vq[k] * 4) << 2),
                      Vb4[varr[k]] + (size_t)vd[k] * 256 + cn * 16 + vq[k]);
            CPA_COMMIT();
            CPA_WAIT1();
        } else {
            CPA_WAIT0();
        }
        __syncthreads();

        const uint32_t* VH = ST + buf * 2 * VBUF;
        const uint32_t* VL = VH + VBUF;
        const int vrow = (nd * 8 + gid) * 68;

        #pragma unroll
        for (int kk = 0; kk < 4; ++kk) {
            const int kp = kh * 4 + kk;
            const int k0 = (c << 7) + (kp << 4);
            uint2 A0 = *(uint2*)&sc_u[gid * RS + k0 + 2 * tig];
            uint2 A1 = *(uint2*)&sc_u[(gid + 8) * RS + k0 + 2 * tig];
            uint2 A2 = *(uint2*)&sc_u[gid * RS + k0 + 8 + 2 * tig];
            uint2 A3 = *(uint2*)&sc_u[(gid + 8) * RS + k0 + 8 + 2 * tig];
            uint32_t ah[4] = {A0.x, A1.x, A2.x, A3.x};
            uint32_t al[4] = {A0.y, A1.y, A2.y, A3.y};

            const int s2l = kp * 8;
            uint32_t b0h = VH[vrow + s2l + tig];
            uint32_t b1h = VH[vrow + s2l + 4 + tig];
            uint32_t b0l = VL[vrow + s2l + tig];
            uint32_t b1l = VL[vrow + s2l + 4 + tig];
            mma_bf16(cacc, ah, b0h, b1h);
            mma_bf16(cacc, ah, b0l, b1l);
            mma_bf16(cacc, al, b0h, b1h);
        }
        __syncthreads();
    }

    // ---- reduce (red aliases sc; all PV reads done) ----
    *(float2*)&red[(kh << 10) + gid * 64 + nd * 8 + 2 * tig]       = make_float2(cacc[0], cacc[1]);
    *(float2*)&red[(kh << 10) + (gid + 8) * 64 + nd * 8 + 2 * tig] = make_float2(cacc[2], cacc[3]);
    __syncthreads();

    for (int i = tid; i < TM * Dq; i += 512) {
        int r = i >> 6, d = i & 63;
        float o = (red[i] + red[1024 + i]) * inv[r];
        g_O[((size_t)(b * Sq + t0 + r)) * Eq + h * Dq + d] = o;
    }
}

// ---------------------------------------------------------------------------
// Launch
// ---------------------------------------------------------------------------
extern "C" void kernel_launch(void* const* d_in, const int* in_sizes, int n_in,
                              void* d_out, int out_size)
{
    const float* query = (const float*)d_in[0];
    const float* key   = (const float*)d_in[1];
    const float* value = (const float*)d_in[2];
    const float* Wq    = (const float*)d_in[3];
    const float* bq    = (const float*)d_in[4];
    const float* Wk    = (const float*)d_in[5];
    const float* bk    = (const float*)d_in[6];
    const float* Wv    = (const float*)d_in[7];
    const float* bv    = (const float*)d_in[8];
    const float* Wo    = (const float*)d_in[9];
    const float* bo    = (const float*)d_in[10];
    const float* ts    = (const float*)d_in[11];

    cudaFuncSetAttribute(attn_kernel, cudaFuncAttributeMaxDynamicSharedMemorySize,
                         SMEM_FLOATS * 4);

    dim3 gT(Eq / 32, Eq / 32, 4);
    wtrans_kernel<<<gT, dim3(32, 8)>>>(Wq, Wk, Wv, Wo);

    float* wt; cudaGetSymbolAddress((void**)&wt, g_Wt);
    float* gO; cudaGetSymbolAddress((void**)&gO, g_O);

    dim3 gA(Eq / 128, (Bq * Sq) / 128);

    gemm_mma_kernel<<<gA, 256>>>(query, wt + 0 * (size_t)Eq * Eq, bq, ts, 0, nullptr);
    gemm_mma_kernel<<<gA, 256>>>(key,   wt + 1 * (size_t)Eq * Eq, bk, ts, 1, nullptr);
    gemm_mma_kernel<<<gA, 256>>>(value, wt + 2 * (size_t)Eq * Eq, bv, ts, 2, nullptr);

    conv_kernel<<<dim3(8192, 2), 256>>>();

    dim3 gAttn(Sq / TM, Bq * Hq);
    attn_kernel<<<gAttn, 512, SMEM_FLOATS * 4>>>();

    gemm_mma_kernel<<<gA, 256>>>(gO, wt + 3 * (size_t)Eq * Eq, bo, ts, 3, (float*)d_out);
}

// round 9
// speedup vs baseline: 2.5547x; 1.1863x over previous
#include <cuda_runtime.h>
#include <cstdint>

// Problem constants
#define Bq 2
#define Sq 2048
#define Eq 1024
#define Hq 16
#define Dq 64
#define KKq 409           // max(1, int(S*0.2))
#define SCOREMUL 0.15625f // (1/sqrt(64)) / temperature, temperature = 0.8
#define DIAGMUL  1.15f    // 1 + ACH*0.3
#define MASKMUL  1.15f    // 1 + (-DA)*0.3

#define TM 16             // query rows per attention block
#define RS 2052           // sc row stride (floats)
#define WSL 1152          // u32 per warp staging slice

// ---------------------------------------------------------------------------
// Scratch (device globals)
// ---------------------------------------------------------------------------
__device__ float    g_Q [Bq*Hq*Sq*Dq];   // (b,h,s,d)
__device__ float    g_V [Bq*Hq*Sq*Dq];   // (b,h,s,d)
__device__ float    g_O [Bq*Sq*Eq];      // (b,s,e)
__device__ float    g_Wt[4*Eq*Eq];       // Wq^T, Wk^T, Wv^T, Wo^T
__device__ uint32_t g_Kbh[Bq*Hq*Sq*32];  // K bf16 hi, (bh, s, d2)
__device__ uint32_t g_Kbl[Bq*Hq*Sq*32];  // K bf16 lo
__device__ uint32_t g_Vbh[Bq*Hq*Dq*1024];// V bf16 hi, (bh, d, s2)
__device__ uint32_t g_Vbl[Bq*Hq*Dq*1024];// V bf16 lo

// ---------------------------------------------------------------------------
// helpers
// ---------------------------------------------------------------------------
__device__ __forceinline__ uint32_t bfpack(float lo, float hi) {
    uint32_t r;
    asm("cvt.rn.bf16x2.f32 %0, %1, %2;" : "=r"(r) : "f"(hi), "f"(lo));
    return r;
}
__device__ __forceinline__ float bflowf(uint32_t p)  { return __uint_as_float(p << 16); }
__device__ __forceinline__ float bfhighf(uint32_t p) { return __uint_as_float(p & 0xFFFF0000u); }

__device__ __forceinline__ void mma_bf16(float* d, const uint32_t* a, uint32_t b0, uint32_t b1) {
    asm volatile(
        "mma.sync.aligned.m16n8k16.row.col.f32.bf16.bf16.f32 "
        "{%0,%1,%2,%3}, {%4,%5,%6,%7}, {%8,%9}, {%0,%1,%2,%3};"
        : "+f"(d[0]), "+f"(d[1]), "+f"(d[2]), "+f"(d[3])
        : "r"(a[0]), "r"(a[1]), "r"(a[2]), "r"(a[3]), "r"(b0), "r"(b1));
}

__device__ __forceinline__ unsigned fmap(float f) {
    unsigned u = __float_as_uint(f);
    return (u & 0x80000000u) ? ~u : (u | 0x80000000u);
}

__device__ __forceinline__ uint32_t smem_u32(const void* p) {
    uint32_t a;
    asm("{ .reg .u64 t; cvta.to.shared.u64 t, %1; cvt.u32.u64 %0, t; }" : "=r"(a) : "l"(p));
    return a;
}
__device__ __forceinline__ void cpa16(uint32_t dst, const void* src) {
    asm volatile("cp.async.cg.shared.global [%0], [%1], 16;" :: "r"(dst), "l"(src) : "memory");
}
#define CPA_COMMIT() asm volatile("cp.async.commit_group;" ::: "memory")
#define CPA_WAIT1()  asm volatile("cp.async.wait_group 1;" ::: "memory")
#define CPA_WAIT0()  asm volatile("cp.async.wait_group 0;" ::: "memory")

// ---------------------------------------------------------------------------
// Weight transpose: g_Wt[z] = W(z)^T
// ---------------------------------------------------------------------------
__global__ void wtrans_kernel(const float* __restrict__ Wq, const float* __restrict__ Wk,
                              const float* __restrict__ Wv, const float* __restrict__ Wo)
{
    __shared__ float t[32][33];
    const int z = blockIdx.z;
    const float* W = (z == 0) ? Wq : (z == 1) ? Wk : (z == 2) ? Wv : Wo;
    float* out = g_Wt + (size_t)z * Eq * Eq;
    const int x0 = blockIdx.x * 32, y0 = blockIdx.y * 32;
    const int tx = threadIdx.x, ty = threadIdx.y;
    #pragma unroll
    for (int i = 0; i < 32; i += 8)
        t[ty + i][tx] = W[(size_t)(y0 + ty + i) * Eq + x0 + tx];
    __syncthreads();
    #pragma unroll
    for (int i = 0; i < 32; i += 8)
        out[(size_t)(x0 + ty + i) * Eq + y0 + tx] = t[tx][ty + i];
}

// ---------------------------------------------------------------------------
// Convert V fp32 -> bf16 hi/lo (bh, d, s2)
// ---------------------------------------------------------------------------
__global__ __launch_bounds__(256) void conv_v_kernel()
{
    const int i = blockIdx.x * 256 + threadIdx.x;   // 0 .. 2M-1
    const int bh = i >> 16, rem = i & 65535;
    const int d = rem >> 10, s2 = rem & 1023;
    float v0 = g_V[(((size_t)(bh << 11) + 2 * s2)     << 6) + d];
    float v1 = g_V[(((size_t)(bh << 11) + 2 * s2 + 1) << 6) + d];
    uint32_t hh = bfpack(v0, v1);
    g_Vbh[i] = hh;
    g_Vbl[i] = bfpack(v0 - bflowf(hh), v1 - bfhighf(hh));
}

// ---------------------------------------------------------------------------
// Fused QKV bf16x3 mma GEMM (mode = blockIdx.z):
//   0: query@Wq -> g_Q (b,h,s,d) +bq
//   1: key@Wk   -> g_Kbh/g_Kbl directly (bf16 hi/lo, (bh,s,d2)), (+bk)*ts[h]
//   2: value@Wv -> g_V (b,h,s,d) +bv
// ---------------------------------------------------------------------------
#define SROW 20

__device__ __forceinline__ void gemm_core(
    const float* __restrict__ A, const float* __restrict__ Bt,
    uint32_t* Ahi, uint32_t* Alo, uint32_t* Bhi, uint32_t* Blo,
    int m0, int n0, float acc[2][8][4])
{
    const int tid  = threadIdx.x;
    const int wid  = tid >> 5, lane = tid & 31;
    const int gid  = lane >> 2, tig = lane & 3;
    const int wm   = wid & 3,  wn  = wid >> 2;

    const float4* pa[4];
    const float4* pb[4];
    int so[4];
    #pragma unroll
    for (int j = 0; j < 4; ++j) {
        int f4  = tid + j * 256;
        int row = f4 >> 3;
        int cq  = f4 & 7;
        pa[j] = (const float4*)(A  + (size_t)(m0 + row) * Eq) + cq;
        pb[j] = (const float4*)(Bt + (size_t)(n0 + row) * Eq) + cq;
        so[j] = row * SROW + cq * 2;
    }

    float4 ra[4], rb[4];
    #pragma unroll
    for (int j = 0; j < 4; ++j) { ra[j] = pa[j][0]; rb[j] = pb[j][0]; }

    for (int kc = 0; kc < 32; ++kc) {
        __syncthreads();
        #pragma unroll
        for (int j = 0; j < 4; ++j) {
            uint32_t h0 = bfpack(ra[j].x, ra[j].y);
            uint32_t h1 = bfpack(ra[j].z, ra[j].w);
            Ahi[so[j]]     = h0;
            Ahi[so[j] + 1] = h1;
            Alo[so[j]]     = bfpack(ra[j].x - bflowf(h0), ra[j].y - bfhighf(h0));
            Alo[so[j] + 1] = bfpack(ra[j].z - bflowf(h1), ra[j].w - bfhighf(h1));
            uint32_t g0 = bfpack(rb[j].x, rb[j].y);
            uint32_t g1 = bfpack(rb[j].z, rb[j].w);
            Bhi[so[j]]     = g0;
            Bhi[so[j] + 1] = g1;
            Blo[so[j]]     = bfpack(rb[j].x - bflowf(g0), rb[j].y - bfhighf(g0));
            Blo[so[j] + 1] = bfpack(rb[j].z - bflowf(g1), rb[j].w - bfhighf(g1));
        }
        __syncthreads();

        if (kc < 31) {
            #pragma unroll
            for (int j = 0; j < 4; ++j) {
                ra[j] = pa[j][(kc + 1) * 8];
                rb[j] = pb[j][(kc + 1) * 8];
            }
        }

        #pragma unroll
        for (int ks = 0; ks < 2; ++ks) {
            const int kb = ks * 8;
            uint32_t ah[2][4], al[2][4];
            #pragma unroll
            for (int mt = 0; mt < 2; ++mt) {
                const int r0 = wm * 32 + mt * 16 + gid;
                ah[mt][0] = Ahi[r0 * SROW + kb + tig];
                ah[mt][1] = Ahi[(r0 + 8) * SROW + kb + tig];
                ah[mt][2] = Ahi[r0 * SROW + kb + tig + 4];
                ah[mt][3] = Ahi[(r0 + 8) * SROW + kb + tig + 4];
                al[mt][0] = Alo[r0 * SROW + kb + tig];
                al[mt][1] = Alo[(r0 + 8) * SROW + kb + tig];
                al[mt][2] = Alo[r0 * SROW + kb + tig + 4];
                al[mt][3] = Alo[(r0 + 8) * SROW + kb + tig + 4];
            }
            #pragma unroll
            for (int nt = 0; nt < 8; ++nt) {
                const int n = wn * 64 + nt * 8 + gid;
                uint32_t bh0 = Bhi[n * SROW + kb + tig];
                uint32_t bh1 = Bhi[n * SROW + kb + tig + 4];
                uint32_t bl0 = Blo[n * SROW + kb + tig];
                uint32_t bl1 = Blo[n * SROW + kb + tig + 4];
                #pragma unroll
                for (int mt = 0; mt < 2; ++mt) {
                    mma_bf16(acc[mt][nt], ah[mt], bh0, bh1);
                    mma_bf16(acc[mt][nt], ah[mt], bl0, bl1);
                    mma_bf16(acc[mt][nt], al[mt], bh0, bh1);
                }
            }
        }
    }
}

__global__ __launch_bounds__(256, 2) void gemm_qkv_kernel(
    const float* __restrict__ query, const float* __restrict__ key,
    const float* __restrict__ value, const float* __restrict__ wt,
    const float* __restrict__ bq, const float* __restrict__ bk,
    const float* __restrict__ bv, const float* __restrict__ ts)
{
    __shared__ uint32_t sb[4 * 128 * SROW];
    const int mode = blockIdx.z;
    const float* A    = (mode == 0) ? query : (mode == 1) ? key : value;
    const float* Bt   = wt + (size_t)mode * Eq * Eq;
    const float* bias = (mode == 0) ? bq : (mode == 1) ? bk : bv;

    const int tid = threadIdx.x;
    const int wid = tid >> 5, lane = tid & 31;
    const int gid = lane >> 2, tig = lane & 3;
    const int wm  = wid & 3,  wn  = wid >> 2;
    const int m0  = blockIdx.y * 128, n0 = blockIdx.x * 128;

    float acc[2][8][4];
    #pragma unroll
    for (int mt = 0; mt < 2; ++mt)
        #pragma unroll
        for (int nt = 0; nt < 8; ++nt)
            #pragma unroll
            for (int c = 0; c < 4; ++c) acc[mt][nt][c] = 0.0f;

    gemm_core(A, Bt, sb, sb + 128 * SROW, sb + 2 * 128 * SROW, sb + 3 * 128 * SROW,
              m0, n0, acc);

    #pragma unroll
    for (int mt = 0; mt < 2; ++mt) {
        const int row = m0 + wm * 32 + mt * 16 + gid;
        const int bb = row >> 11, s = row & (Sq - 1);
        #pragma unroll
        for (int nt = 0; nt < 8; ++nt) {
            const int col = n0 + wn * 64 + nt * 8 + 2 * tig;
            const int h = col >> 6, dd = col & 63;
            const float* d = acc[mt][nt];
            float2 bvv = *(const float2*)(bias + col);
            if (mode == 1) {
                const float tv = ts[h];
                float v0 = (d[0] + bvv.x) * tv, v1 = (d[1] + bvv.y) * tv;
                float v2 = (d[2] + bvv.x) * tv, v3 = (d[3] + bvv.y) * tv;
                size_t idx = ((size_t)(bb * Hq + h) << 16) + s * 32 + (dd >> 1);
                uint32_t h0 = bfpack(v0, v1);
                g_Kbh[idx] = h0;
                g_Kbl[idx] = bfpack(v0 - bflowf(h0), v1 - bfhighf(h0));
                uint32_t h1 = bfpack(v2, v3);
                g_Kbh[idx + 256] = h1;
                g_Kbl[idx + 256] = bfpack(v2 - bflowf(h1), v3 - bfhighf(h1));
            } else {
                float* base = (mode == 0) ? g_Q : g_V;
                float* dst = base + ((size_t)(bb * Hq + h) * Sq + s) * Dq + dd;
                *(float2*)(dst)          = make_float2(d[0] + bvv.x, d[1] + bvv.y);
                *(float2*)(dst + 8 * Dq) = make_float2(d[2] + bvv.x, d[3] + bvv.y);
            }
        }
    }
}

// ---------------------------------------------------------------------------
// Output GEMM: d_out = g_O @ Wo + bo
// ---------------------------------------------------------------------------
__global__ __launch_bounds__(256, 2) void gemm_out_kernel(
    const float* __restrict__ wt, const float* __restrict__ bo,
    float* __restrict__ Cout)
{
    __shared__ uint32_t sb[4 * 128 * SROW];
    const int tid = threadIdx.x;
    const int wid = tid >> 5, lane = tid & 31;
    const int gid = lane >> 2, tig = lane & 3;
    const int wm  = wid & 3,  wn  = wid >> 2;
    const int m0  = blockIdx.y * 128, n0 = blockIdx.x * 128;

    float acc[2][8][4];
    #pragma unroll
    for (int mt = 0; mt < 2; ++mt)
        #pragma unroll
        for (int nt = 0; nt < 8; ++nt)
            #pragma unroll
            for (int c = 0; c < 4; ++c) acc[mt][nt][c] = 0.0f;

    gemm_core(g_O, wt + 3 * (size_t)Eq * Eq,
              sb, sb + 128 * SROW, sb + 2 * 128 * SROW, sb + 3 * 128 * SROW,
              m0, n0, acc);

    #pragma unroll
    for (int mt = 0; mt < 2; ++mt) {
        const int row = m0 + wm * 32 + mt * 16 + gid;
        #pragma unroll
        for (int nt = 0; nt < 8; ++nt) {
            const int col = n0 + wn * 64 + nt * 8 + 2 * tig;
            const float* d = acc[mt][nt];
            float2 bvv = *(const float2*)(bo + col);
            *(float2*)(Cout + (size_t)row * Eq + col) =
                make_float2(d[0] + bvv.x, d[1] + bvv.y);
            *(float2*)(Cout + (size_t)(row + 8) * Eq + col) =
                make_float2(d[2] + bvv.x, d[3] + bvv.y);
        }
    }
}

// ---------------------------------------------------------------------------
// Fused attention v6: warp-decoupled, warp-private double-buffered staging.
// Smem (floats):
//   sc [16][2052]  scores -> packed bf16 hi/lo probs   131,328 B
//   ST 18432 fl    16 warp slices x 1152 u32 (K/V stage, hist, PV partials)
//   Qs [16][66], inv[16]
// Only 3 block-wide syncs (QK->middle, middle->PV, PV->reduce) + Q-load sync.
// ---------------------------------------------------------------------------
#define OFF_ST   (TM * RS)               // 32832
#define OFF_Q    (OFF_ST + 18432)        // 51264
#define OFF_INV  (OFF_Q + 16*66)         // 52320
#define SMEM_FLOATS (OFF_INV + 16)       // 52336 -> 209,344 B

__global__ __launch_bounds__(512, 1) void attn_kernel()
{
    extern __shared__ float smem[];
    float*    sc   = smem;
    uint32_t* sc_u = (uint32_t*)smem;
    uint32_t* ST   = (uint32_t*)(smem + OFF_ST);
    float*    Qs   = smem + OFF_Q;
    float*    inv  = smem + OFF_INV;

    const int tid = threadIdx.x;
    const int w   = tid >> 5, lane = tid & 31;
    const int gid = lane >> 2, tig = lane & 3;
    const int bh  = blockIdx.y;
    const int t0  = blockIdx.x * TM;
    const int b   = bh >> 4, h = bh & 15;

    const float* Qg = g_Q + (size_t)bh * Sq * Dq;
    const uint4* Kb4[2] = { (const uint4*)(g_Kbh + ((size_t)bh << 16)),
                            (const uint4*)(g_Kbl + ((size_t)bh << 16)) };
    const uint4* Vb4[2] = { (const uint4*)(g_Vbh + ((size_t)bh << 16)),
                            (const uint4*)(g_Vbl + ((size_t)bh << 16)) };

    const uint32_t* Wbuf = ST + w * WSL;                 // this warp's slice
    const uint32_t wb_b  = smem_u32(ST) + ((w * WSL) << 2);

    // staging map: 4 uint4 per lane per chunk
    int sarr[4], srr[4], sq[4];
    #pragma unroll
    for (int k = 0; k < 4; ++k) {
        int idx = lane + k * 32;          // 0..127
        sarr[k] = idx >> 6;               // hi/lo array
        srr[k]  = (idx >> 3) & 7;         // local row
        sq[k]   = idx & 7;                // uint4 within row
    }
    const int nd = w & 7, kh = w >> 3;    // PV warp roles

    // ---- prefetch K chunk 0 (buf 0) ----
    #pragma unroll
    for (int k = 0; k < 4; ++k)
        cpa16(wb_b + ((sarr[k] * 288 + srr[k] * 36 + sq[k] * 4) << 2),
              Kb4[sarr[k]] + ((w * 8 + srr[k]) * 8 + sq[k]));
    CPA_COMMIT();

    // ---- Q stage ----
    for (int i = tid; i < TM * Dq; i += 512) {
        int r = i >> 6, d = i & 63;
        Qs[r * 66 + d] = Qg[(size_t)(t0 + r) * Dq + d];
    }
    __syncthreads();

    // ---- Q fragments ----
    uint32_t ahq[4][4], alq[4][4];
    #pragma unroll
    for (int ks = 0; ks < 4; ++ks) {
        float2 q[4];
        q[0] = *(float2*)&Qs[gid * 66 + ks * 16 + 2 * tig];
        q[1] = *(float2*)&Qs[(gid + 8) * 66 + ks * 16 + 2 * tig];
        q[2] = *(float2*)&Qs[gid * 66 + ks * 16 + 2 * tig + 8];
        q[3] = *(float2*)&Qs[(gid + 8) * 66 + ks * 16 + 2 * tig + 8];
        #pragma unroll
        for (int j = 0; j < 4; ++j) {
            uint32_t hh = bfpack(q[j].x, q[j].y);
            ahq[ks][j] = hh;
            alq[ks][j] = bfpack(q[j].x - bflowf(hh), q[j].y - bfhighf(hh));
        }
    }

    // ---- QK^T: 16 chunks of 128 s, warp-decoupled ----
    for (int c = 0; c < 16; ++c) {
        const int buf = c & 1;
        if (c < 15) {
            const int bo2 = (buf ^ 1) * 576;
            #pragma unroll
            for (int k = 0; k < 4; ++k)
                cpa16(wb_b + ((bo2 + sarr[k] * 288 + srr[k] * 36 + sq[k] * 4) << 2),
                      Kb4[sarr[k]] + (((c + 1) * 128 + w * 8 + srr[k]) * 8 + sq[k]));
            CPA_COMMIT();
            CPA_WAIT1();
        } else {
            CPA_WAIT0();
        }
        __syncwarp();

        const uint32_t* KH = Wbuf + buf * 576;
        const uint32_t* KL = KH + 288;
        float cf[4] = {0.f, 0.f, 0.f, 0.f};
        #pragma unroll
        for (int ks = 0; ks < 4; ++ks) {
            uint32_t b0h = KH[gid * 36 + ks * 8 + tig];
            uint32_t b1h = KH[gid * 36 + ks * 8 + 4 + tig];
            uint32_t b0l = KL[gid * 36 + ks * 8 + tig];
            uint32_t b1l = KL[gid * 36 + ks * 8 + 4 + tig];
            mma_bf16(cf, ahq[ks], b0h, b1h);
            mma_bf16(cf, ahq[ks], b0l, b1l);
            mma_bf16(cf, alq[ks], b0h, b1h);
        }
        const int sg = (c << 7) + w * 8 + 2 * tig;
        float v0 = cf[0] * SCOREMUL; if (sg     == t0 + gid)     v0 *= DIAGMUL;
        float v1 = cf[1] * SCOREMUL; if (sg + 1 == t0 + gid)     v1 *= DIAGMUL;
        float v2 = cf[2] * SCOREMUL; if (sg     == t0 + gid + 8) v2 *= DIAGMUL;
        float v3 = cf[3] * SCOREMUL; if (sg + 1 == t0 + gid + 8) v3 *= DIAGMUL;
        *(float2*)&sc[gid * RS + sg]       = make_float2(v0, v1);
        *(float2*)&sc[(gid + 8) * RS + sg] = make_float2(v2, v3);
        __syncwarp();
    }
    __syncthreads();   // all scores written

    // ---- middle (one warp per row): top-k radix + softmax + bf16 pack ----
    {
        const int r = w;
        unsigned* hw = (unsigned*)(ST + w * WSL);   // own slice (K bufs dead)

        unsigned thrp = 0;
        int kneed = KKq;

        for (int shift = 24; shift >= 0; shift -= 8) {
            #pragma unroll
            for (int j = 0; j < 8; ++j) hw[lane + j * 32] = 0;
            __syncwarp();
            for (int i = lane; i < Sq; i += 32) {
                unsigned u = fmap(sc[r * RS + i]);
                bool ok = (shift == 24) || (((u ^ thrp) >> (shift + 8)) == 0);
                if (ok) atomicAdd(&hw[(u >> shift) & 255], 1u);
            }
            __syncwarp();
            const int b0 = (31 - lane) * 8;
            unsigned cb[8], cl = 0;
            #pragma unroll
            for (int j = 0; j < 8; ++j) { cb[j] = hw[b0 + j]; cl += cb[j]; }
            unsigned S = cl;
            #pragma unroll
            for (int o = 1; o < 32; o <<= 1) {
                unsigned x = __shfl_up_sync(0xFFFFFFFFu, S, o);
                if (lane >= o) S += x;
            }
            unsigned excl = S - cl;
            bool has = (excl < (unsigned)kneed) && ((unsigned)kneed <= S);
            unsigned bal = __ballot_sync(0xFFFFFFFFu, has);
            int src = __ffs(bal) - 1;
            int bsel = 0, nk = 0;
            if (lane == src) {
                int rem = kneed - (int)excl;
                #pragma unroll
                for (int j = 7; j >= 0; --j) {
                    int cnt = (int)cb[j];
                    if (rem <= cnt) { bsel = b0 + j; nk = rem; break; }
                    rem -= cnt;
                }
            }
            bsel  = __shfl_sync(0xFFFFFFFFu, bsel, src);
            nk    = __shfl_sync(0xFFFFFFFFu, nk, src);
            thrp |= ((unsigned)bsel) << shift;
            kneed = nk;
            __syncwarp();
        }

        float mx = -3.402823466e+38f;
        for (int i = lane; i < Sq; i += 32) {
            float v = sc[r * RS + i];
            if (fmap(v) >= thrp) v *= MASKMUL;
            sc[r * RS + i] = v;
            mx = fmaxf(mx, v);
        }
        #pragma unroll
        for (int o = 16; o; o >>= 1) mx = fmaxf(mx, __shfl_xor_sync(0xFFFFFFFFu, mx, o));

        float sum = 0.0f;
        #pragma unroll 4
        for (int j = 0; j < 32; ++j) {
            const int p = lane + 32 * j;
            float2 v = *(float2*)&sc[r * RS + 2 * p];
            float e0 = __expf(v.x - mx);
            float e1 = __expf(v.y - mx);
            sum += e0 + e1;
            uint32_t hh = bfpack(e0, e1);
            uint32_t ll = bfpack(e0 - bflowf(hh), e1 - bfhighf(hh));
            uint2 pk; pk.x = hh; pk.y = ll;
            *(uint2*)&sc_u[r * RS + 2 * p] = pk;
        }
        #pragma unroll
        for (int o = 16; o; o >>= 1) sum += __shfl_xor_sync(0xFFFFFFFFu, sum, o);
        if (lane == 0) inv[r] = 1.0f / sum;
    }

    // prefetch V chunk 0 (buf 0) into own slice (own middle work is done)
    #pragma unroll
    for (int k = 0; k < 4; ++k)
        cpa16(wb_b + ((sarr[k] * 288 + srr[k] * 36 + sq[k] * 4) << 2),
              Vb4[sarr[k]] + ((nd * 8 + srr[k]) * 256 + kh * 8 + sq[k]));
    CPA_COMMIT();
    __syncthreads();   // all rows packed before PV A-fragment reads

    // ---- P @ V: 16 chunks of 128 s, warp-decoupled ----
    float cacc[4] = {0.f, 0.f, 0.f, 0.f};

    for (int c = 0; c < 16; ++c) {
        const int buf = c & 1;
        if (c < 15) {
            const int bo2 = (buf ^ 1) * 576;
            #pragma unroll
            for (int k = 0; k < 4; ++k)
                cpa16(wb_b + ((bo2 + sarr[k] * 288 + srr[k] * 36 + sq[k] * 4) << 2),
                      Vb4[sarr[k]] + ((nd * 8 + srr[k]) * 256 + (c + 1) * 16 + kh * 8 + sq[k]));
            CPA_COMMIT();
            CPA_WAIT1();
        } else {
            CPA_WAIT0();
        }
        __syncwarp();

        const uint32_t* VH = Wbuf + buf * 576;
        const uint32_t* VL = VH + 288;

        #pragma unroll
        for (int kk = 0; kk < 4; ++kk) {
            const int kp = kh * 4 + kk;
            const int k0 = (c << 7) + (kp << 4);
            uint2 A0 = *(uint2*)&sc_u[gid * RS + k0 + 2 * tig];
            uint2 A1 = *(uint2*)&sc_u[(gid + 8) * RS + k0 + 2 * tig];
            uint2 A2 = *(uint2*)&sc_u[gid * RS + k0 + 8 + 2 * tig];
            uint2 A3 = *(uint2*)&sc_u[(gid + 8) * RS + k0 + 8 + 2 * tig];
            uint32_t ah[4] = {A0.x, A1.x, A2.x, A3.x};
            uint32_t al[4] = {A0.y, A1.y, A2.y, A3.y};

            uint32_t b0h = VH[gid * 36 + kk * 8 + tig];
            uint32_t b1h = VH[gid * 36 + kk * 8 + 4 + tig];
            uint32_t b0l = VL[gid * 36 + kk * 8 + tig];
            uint32_t b1l = VL[gid * 36 + kk * 8 + 4 + tig];
            mma_bf16(cacc, ah, b0h, b1h);
            mma_bf16(cacc, ah, b0l, b1l);
            mma_bf16(cacc, al, b0h, b1h);
        }
        __syncwarp();
    }

    // ---- partials into own slice, reduce across kh, write g_O ----
    {
        float* PS = (float*)(ST + w * WSL);   // own slice; own V bufs dead
        PS[gid * 8 + 2 * tig]           = cacc[0];
        PS[gid * 8 + 2 * tig + 1]       = cacc[1];
        PS[(gid + 8) * 8 + 2 * tig]     = cacc[2];
        PS[(gid + 8) * 8 + 2 * tig + 1] = cacc[3];
    }
    __syncthreads();

    {
        const float* PSb = (const float*)ST;
        for (int i = tid; i < TM * Dq; i += 512) {
            int r = i >> 6, d = i & 63;
            int n2 = d >> 3, dd = d & 7;
            float o = (PSb[(size_t)n2 * WSL + r * 8 + dd] +
                       PSb[(size_t)(8 + n2) * WSL + r * 8 + dd]) * inv[r];
            g_O[((size_t)(b * Sq + t0 + r)) * Eq + h * Dq + d] = o;
        }
    }
}

// ---------------------------------------------------------------------------
// Launch
// ---------------------------------------------------------------------------
extern "C" void kernel_launch(void* const* d_in, const int* in_sizes, int n_in,
                              void* d_out, int out_size)
{
    const float* query = (const float*)d_in[0];
    const float* key   = (const float*)d_in[1];
    const float* value = (const float*)d_in[2];
    const float* Wq    = (const float*)d_in[3];
    const float* bq    = (const float*)d_in[4];
    const float* Wk    = (const float*)d_in[5];
    const float* bk    = (const float*)d_in[6];
    const float* Wv    = (const float*)d_in[7];
    const float* bv    = (const float*)d_in[8];
    const float* Wo    = (const float*)d_in[9];
    const float* bo    = (const float*)d_in[10];
    const float* ts    = (const float*)d_in[11];

    cudaFuncSetAttribute(attn_kernel, cudaFuncAttributeMaxDynamicSharedMemorySize,
                         SMEM_FLOATS * 4);

    dim3 gT(Eq / 32, Eq / 32, 4);
    wtrans_kernel<<<gT, dim3(32, 8)>>>(Wq, Wk, Wv, Wo);

    float* wt; cudaGetSymbolAddress((void**)&wt, g_Wt);

    dim3 gQKV(Eq / 128, (Bq * Sq) / 128, 3);
    gemm_qkv_kernel<<<gQKV, 256>>>(query, key, value, wt, bq, bk, bv, ts);

    conv_v_kernel<<<8192, 256>>>();

    dim3 gAttn(Sq / TM, Bq * Hq);
    attn_kernel<<<gAttn, 512, SMEM_FLOATS * 4>>>();

    dim3 gO(Eq / 128, (Bq * Sq) / 128);
    gemm_out_kernel<<<gO, 256>>>(wt, bo, (float*)d_out);
}